// round 3
// baseline (speedup 1.0000x reference)
#include <cuda_runtime.h>

#define Nn 200000
#define Ee 6400000
#define Gg 1024
#define C  32
#define INC 128
#define EPSF 1e-5f
#define SBLK 128          // blocks for node-level BN stats
#define SBLK_G 8          // blocks for graph-level BN stats

// ------------------------- scratch (device globals) -------------------------
__device__ int    g_src[Ee];
__device__ int    g_dst[Ee];
__device__ float  g_w[Ee];
__device__ float  g_deg[Nn];
__device__ float  g_dis[Nn];
__device__ float  g_dinv[Nn];
__device__ float  g_h[Nn * C];        // transformed features (scatter source)
__device__ float  g_aggA[Nn * C];
__device__ float  g_aggB[Nn * C];
__device__ float  g_mlpA[Gg * C];
__device__ float  g_mlpB[Gg * C];
__device__ float  g_pool[Gg * C];
__device__ float  g_part[4 * SBLK * 64];  // per-pass, per-block {sum[32], sumsq[32]}
__device__ float  g_bnco[4 * 64];         // per-pass {scale[32], shift[32]}
__device__ int    g_is64;                 // 1 if index inputs are int64, 0 if int32

__device__ __forceinline__ const float* selbuf(int s) {
    if (s == 0) return g_aggA;
    if (s == 1) return g_aggB;
    if (s == 2) return g_mlpA;
    return g_mlpB;
}

// ------------------------- dtype detection -------------------------
// If edge_index is int64 (values < 2^31), the high word of every entry is 0.
// If int32, the "odd words" are real node ids (~uniform in [0,200000)) and
// are essentially never all zero across 1024 samples.
__global__ void k_detect(const unsigned int* __restrict__ w) {
    unsigned int acc = 0;
    for (int i = threadIdx.x; i < 2048; i += 32)
        if (i & 1) acc |= w[i];
#pragma unroll
    for (int o = 16; o; o >>= 1) acc |= __shfl_down_sync(0xffffffffu, acc, o);
    if (threadIdx.x == 0) g_is64 = (acc == 0u) ? 1 : 0;
}

// ------------------------- init -------------------------
__global__ void k_zero() {
    int idx = blockIdx.x * blockDim.x + threadIdx.x;
    int stride = gridDim.x * blockDim.x;
    for (int i = idx; i < Nn; i += stride)      g_deg[i]  = 0.f;
    for (int i = idx; i < Gg * C; i += stride)  g_pool[i] = 0.f;
}

// convert indices -> clamped int32, count in-degree
__global__ void k_prep_edges(const void* __restrict__ eiv) {
    int e = blockIdx.x * blockDim.x + threadIdx.x;
    if (e >= Ee) return;
    int s, d;
    if (g_is64) {
        const long long* ei = (const long long*)eiv;
        s = (int)ei[e];
        d = (int)ei[Ee + e];
    } else {
        const int* ei = (const int*)eiv;
        s = ei[e];
        d = ei[Ee + e];
    }
    s = min(max(s, 0), Nn - 1);
    d = min(max(d, 0), Nn - 1);
    g_src[e] = s;
    g_dst[e] = d;
    atomicAdd(&g_deg[d], 1.0f);
}

__global__ void k_prep_nodes() {
    int i = blockIdx.x * blockDim.x + threadIdx.x;
    if (i >= Nn) return;
    float d = g_deg[i] + 1.0f;
    g_dinv[i] = 1.0f / d;
    g_dis[i]  = rsqrtf(d);
}

__global__ void k_edge_w() {
    int e = blockIdx.x * blockDim.x + threadIdx.x;
    if (e >= Ee) return;
    g_w[e] = g_dis[g_src[e]] * g_dis[g_dst[e]];
}

// ------------------------- layer 1 matmul (128 -> 32) -------------------------
// warp per node; W1 staged in smem; x row in 4 regs, broadcast via shfl
__global__ void k_mm1(const float* __restrict__ x,
                      const float* __restrict__ W1,
                      const float* __restrict__ b1) {
    __shared__ float Ws[INC * C];
    for (int t = threadIdx.x; t < INC * C; t += blockDim.x) Ws[t] = W1[t];
    __syncthreads();
    int warp = threadIdx.x >> 5, lane = threadIdx.x & 31;
    int i = blockIdx.x * 8 + warp;
    if (i >= Nn) return;
    float xr[4];
#pragma unroll
    for (int j = 0; j < 4; j++) xr[j] = x[i * INC + j * 32 + lane];
    float acc = 0.f;
#pragma unroll
    for (int k = 0; k < INC; k++) {
        float xk = __shfl_sync(0xffffffffu, xr[k >> 5], k & 31);
        acc = fmaf(xk, Ws[k * C + lane], acc);
    }
    g_h[i * C + lane]    = acc;
    g_aggA[i * C + lane] = acc * g_dinv[i] + b1[lane];
}

// ------------------------- edge scatter (the hot kernel) -------------------------
// warp handles 4 consecutive edges; lane = feature channel
__global__ void k_scat(int sel) {
    float* __restrict__ agg = (float*)selbuf(sel);
    const float* __restrict__ h = g_h;
    int lane = threadIdx.x & 31;
    int warp = blockIdx.x * (blockDim.x >> 5) + (threadIdx.x >> 5);
    int base = warp * 4;
    if (base >= Ee) return;

    int   s0 = g_src[base + 0], s1 = g_src[base + 1], s2 = g_src[base + 2], s3 = g_src[base + 3];
    int   d0 = g_dst[base + 0], d1 = g_dst[base + 1], d2 = g_dst[base + 2], d3 = g_dst[base + 3];
    float w0 = g_w[base + 0],   w1 = g_w[base + 1],   w2 = g_w[base + 2],   w3 = g_w[base + 3];

    float v0 = h[s0 * C + lane] * w0;
    float v1 = h[s1 * C + lane] * w1;
    float v2 = h[s2 * C + lane] * w2;
    float v3 = h[s3 * C + lane] * w3;

    atomicAdd(&agg[d0 * C + lane], v0);
    atomicAdd(&agg[d1 * C + lane], v1);
    atomicAdd(&agg[d2 * C + lane], v2);
    atomicAdd(&agg[d3 * C + lane], v3);
}

// ------------------------- BN stats: per-block fp32 partials -------------------------
__global__ void k_stats(int sel, int n, int pass) {
    const float* __restrict__ a = selbuf(sel);
    int lane = threadIdx.x & 31, warp = threadIdx.x >> 5;
    int nwt = gridDim.x * 8;
    float s = 0.f, q = 0.f;
    for (int i = blockIdx.x * 8 + warp; i < n; i += nwt) {
        float v = a[i * C + lane];
        s += v;
        q += v * v;
    }
    __shared__ float ss[8][32], sq[8][32];
    ss[warp][lane] = s;
    sq[warp][lane] = q;
    __syncthreads();
    if (warp == 0) {
        float S = 0.f, Q = 0.f;
#pragma unroll
        for (int w = 0; w < 8; w++) { S += ss[w][lane]; Q += sq[w][lane]; }
        g_part[pass * (SBLK * 64) + blockIdx.x * 64 + lane]      = S;
        g_part[pass * (SBLK * 64) + blockIdx.x * 64 + 32 + lane] = Q;
    }
}

// finalize: sum partials (fp64 registers only), emit scale/shift per channel
__global__ void k_finalize(int pass, int nb, float n,
                           const float* __restrict__ gamma,
                           const float* __restrict__ beta) {
    int c = threadIdx.x;   // 32 threads
    double S = 0.0, Q = 0.0;
    const float* p = &g_part[pass * (SBLK * 64)];
    for (int b = 0; b < nb; b++) {
        S += (double)p[b * 64 + c];
        Q += (double)p[b * 64 + 32 + c];
    }
    double m   = S / (double)n;
    double var = Q / (double)n - m * m;
    if (var < 0.0) var = 0.0;
    float r  = rsqrtf((float)var + EPSF);
    float sc = r * gamma[c];
    g_bnco[pass * 64 + c]      = sc;
    g_bnco[pass * 64 + 32 + c] = beta[c] - (float)m * sc;
}

// ------------------------- fused BN-apply + ReLU + matmul (32->32) + agg init ----
__global__ void k_mm_small(int selIn, int selOut, int pass,
                           const float* __restrict__ W,
                           const float* __restrict__ b) {
    const float* __restrict__ ain = selbuf(selIn);
    float* __restrict__ aout = (float*)selbuf(selOut);
    __shared__ float Ws[C * C];
    for (int t = threadIdx.x; t < C * C; t += blockDim.x) Ws[t] = W[t];
    __syncthreads();
    int warp = threadIdx.x >> 5, lane = threadIdx.x & 31;
    int i = blockIdx.x * 8 + warp;
    if (i >= Nn) return;
    float sc = g_bnco[pass * 64 + lane];
    float sh = g_bnco[pass * 64 + 32 + lane];
    float a = ain[i * C + lane];
    float z = fmaxf(a * sc + sh, 0.f);
    float acc = 0.f;
#pragma unroll
    for (int k = 0; k < C; k++) {
        float zk = __shfl_sync(0xffffffffu, z, k);
        acc = fmaf(zk, Ws[k * C + lane], acc);
    }
    g_h[i * C + lane]  = acc;
    aout[i * C + lane] = acc * g_dinv[i] + b[lane];
}

// ------------------------- pooling: sum nodes into graphs -------------------------
__global__ void k_pool(const void* __restrict__ batchv) {
    int lane = threadIdx.x & 31;
    int i = blockIdx.x * (blockDim.x >> 5) + (threadIdx.x >> 5);
    if (i >= Nn) return;
    int b;
    if (g_is64) b = (int)((const long long*)batchv)[i];
    else        b = ((const int*)batchv)[i];
    b = min(max(b, 0), Gg - 1);
    atomicAdd(&g_pool[b * C + lane], g_aggA[i * C + lane]);
}

// ------------------------- MLP head -------------------------
// h1 = pool @ M1 + mb1  (warp per graph)
__global__ void k_mlp_mm1(const float* __restrict__ M1, const float* __restrict__ mb1) {
    __shared__ float Ws[C * C];
    for (int t = threadIdx.x; t < C * C; t += blockDim.x) Ws[t] = M1[t];
    __syncthreads();
    int warp = threadIdx.x >> 5, lane = threadIdx.x & 31;
    int g = blockIdx.x * 8 + warp;
    if (g >= Gg) return;
    float z = g_pool[g * C + lane];
    float acc = mb1[lane];
#pragma unroll
    for (int k = 0; k < C; k++) {
        float zk = __shfl_sync(0xffffffffu, z, k);
        acc = fmaf(zk, Ws[k * C + lane], acc);
    }
    g_mlpA[g * C + lane] = acc;
}

// h2 = relu(bn(h1)) @ M2 + mb2   (bn coefficients precomputed, pass 2)
__global__ void k_mlp_mm2(const float* __restrict__ M2, const float* __restrict__ mb2) {
    __shared__ float Ws[C * C];
    for (int t = threadIdx.x; t < C * C; t += blockDim.x) Ws[t] = M2[t];
    __syncthreads();
    int warp = threadIdx.x >> 5, lane = threadIdx.x & 31;
    int g = blockIdx.x * 8 + warp;
    if (g >= Gg) return;
    float sc = g_bnco[2 * 64 + lane];
    float sh = g_bnco[2 * 64 + 32 + lane];
    float a = g_mlpA[g * C + lane];
    float z = fmaxf(a * sc + sh, 0.f);
    float acc = mb2[lane];
#pragma unroll
    for (int k = 0; k < C; k++) {
        float zk = __shfl_sync(0xffffffffu, z, k);
        acc = fmaf(zk, Ws[k * C + lane], acc);
    }
    g_mlpB[g * C + lane] = acc;
}

// out = relu(bn(h2)) @ M3 + mb3  (bn pass 3)
__global__ void k_mlp_out(const float* __restrict__ M3, const float* __restrict__ mb3,
                          float* __restrict__ out) {
    int lane = threadIdx.x & 31;
    int g = blockIdx.x * (blockDim.x >> 5) + (threadIdx.x >> 5);
    if (g >= Gg) return;
    float sc = g_bnco[3 * 64 + lane];
    float sh = g_bnco[3 * 64 + 32 + lane];
    float v  = g_mlpB[g * C + lane];
    float z  = fmaxf(v * sc + sh, 0.f);
    float t  = z * M3[lane];
#pragma unroll
    for (int o = 16; o; o >>= 1) t += __shfl_down_sync(0xffffffffu, t, o);
    if (lane == 0) out[g] = t + mb3[0];
}

// ------------------------- launch -------------------------
extern "C" void kernel_launch(void* const* d_in, const int* in_sizes, int n_in,
                              void* d_out, int out_size) {
    (void)in_sizes; (void)n_in; (void)out_size;
    const float* x     = (const float*)d_in[0];
    const void*  ei    = d_in[1];
    const void*  batch = d_in[2];
    const float* W1  = (const float*)d_in[3];
    const float* b1  = (const float*)d_in[4];
    const float* gm1 = (const float*)d_in[5];
    const float* be1 = (const float*)d_in[6];
    const float* W2  = (const float*)d_in[7];
    const float* b2  = (const float*)d_in[8];
    const float* gm2 = (const float*)d_in[9];
    const float* be2 = (const float*)d_in[10];
    const float* W3  = (const float*)d_in[11];
    const float* b3  = (const float*)d_in[12];
    const float* M1  = (const float*)d_in[13];
    const float* mb1 = (const float*)d_in[14];
    const float* mg1 = (const float*)d_in[15];
    const float* mbe1= (const float*)d_in[16];
    const float* M2  = (const float*)d_in[17];
    const float* mb2 = (const float*)d_in[18];
    const float* mg2 = (const float*)d_in[19];
    const float* mbe2= (const float*)d_in[20];
    const float* M3  = (const float*)d_in[21];
    const float* mb3 = (const float*)d_in[22];
    float* out = (float*)d_out;

    const int TB = 256;
    k_detect<<<1, 32>>>((const unsigned int*)ei);
    k_zero<<<800, TB>>>();
    k_prep_edges<<<(Ee + TB - 1) / TB, TB>>>(ei);
    k_prep_nodes<<<(Nn + TB - 1) / TB, TB>>>();
    k_edge_w<<<(Ee + TB - 1) / TB, TB>>>();

    // layer 1: conv(x) -> aggA
    k_mm1<<<Nn / 8, TB>>>(x, W1, b1);
    k_scat<<<Ee / 32, TB>>>(0);
    k_stats<<<SBLK, TB>>>(0, Nn, 0);
    k_finalize<<<1, 32>>>(0, SBLK, (float)Nn, gm1, be1);

    // layer 2: relu(bn(aggA)) @ W2 -> aggB
    k_mm_small<<<Nn / 8, TB>>>(0, 1, 0, W2, b2);
    k_scat<<<Ee / 32, TB>>>(1);
    k_stats<<<SBLK, TB>>>(1, Nn, 1);
    k_finalize<<<1, 32>>>(1, SBLK, (float)Nn, gm2, be2);

    // layer 3: relu(bn(aggB)) @ W3 -> aggA (no bn after)
    k_mm_small<<<Nn / 8, TB>>>(1, 0, 1, W3, b3);
    k_scat<<<Ee / 32, TB>>>(0);

    // pool + MLP head
    k_pool<<<Nn / 8, TB>>>(batch);
    k_mlp_mm1<<<Gg / 8, TB>>>(M1, mb1);
    k_stats<<<SBLK_G, TB>>>(2, Gg, 2);
    k_finalize<<<1, 32>>>(2, SBLK_G, (float)Gg, mg1, mbe1);
    k_mlp_mm2<<<Gg / 8, TB>>>(M2, mb2);
    k_stats<<<SBLK_G, TB>>>(3, Gg, 3);
    k_finalize<<<1, 32>>>(3, SBLK_G, (float)Gg, mg2, mbe2);
    k_mlp_out<<<Gg / 8, TB>>>(M3, mb3, out);
}

// round 4
// speedup vs baseline: 1.0033x; 1.0033x over previous
#include <cuda_runtime.h>

#define Nn 200000
#define Ee 6400000
#define Gg 1024
#define C  32
#define INC 128
#define EPSF 1e-5f
#define SBLK 128          // blocks for node-level BN stats
#define SBLK_G 8          // blocks for graph-level BN stats

// ------------------------- scratch (device globals) -------------------------
__device__ int    g_src[Ee];
__device__ int    g_dst[Ee];
__device__ int2   g_edge[Ee];         // CSR-sorted {src, w(bits)} per dst
__device__ int    g_degi[Nn];
__device__ int    g_rowptr[Nn + 1];
__device__ int    g_cursor[Nn];
__device__ float  g_dis[Nn];
__device__ float  g_dinv[Nn];
__device__ float  g_h[Nn * C];        // transformed features (gather source)
__device__ float  g_aggA[Nn * C];
__device__ float  g_aggB[Nn * C];
__device__ float  g_mlpA[Gg * C];
__device__ float  g_mlpB[Gg * C];
__device__ float  g_pool[Gg * C];
__device__ float  g_part[4 * SBLK * 64];  // per-pass, per-block {sum[32], sumsq[32]}
__device__ float  g_bnco[4 * 64];         // per-pass {scale[32], shift[32]}
__device__ int    g_is64;                 // 1 if index inputs are int64, 0 if int32

__device__ __forceinline__ const float* selbuf(int s) {
    if (s == 0) return g_aggA;
    if (s == 1) return g_aggB;
    if (s == 2) return g_mlpA;
    return g_mlpB;
}

// ------------------------- dtype detection -------------------------
__global__ void k_detect(const unsigned int* __restrict__ w) {
    unsigned int acc = 0;
    for (int i = threadIdx.x; i < 2048; i += 32)
        if (i & 1) acc |= w[i];
#pragma unroll
    for (int o = 16; o; o >>= 1) acc |= __shfl_down_sync(0xffffffffu, acc, o);
    if (threadIdx.x == 0) g_is64 = (acc == 0u) ? 1 : 0;
}

// ------------------------- init -------------------------
__global__ void k_zero() {
    int idx = blockIdx.x * blockDim.x + threadIdx.x;
    int stride = gridDim.x * blockDim.x;
    for (int i = idx; i < Nn; i += stride)      g_degi[i] = 0;
    for (int i = idx; i < Gg * C; i += stride)  g_pool[i] = 0.f;
}

// convert indices -> clamped int32, count in-degree
__global__ void k_prep_edges(const void* __restrict__ eiv) {
    int e = blockIdx.x * blockDim.x + threadIdx.x;
    if (e >= Ee) return;
    int s, d;
    if (g_is64) {
        const long long* ei = (const long long*)eiv;
        s = (int)ei[e];
        d = (int)ei[Ee + e];
    } else {
        const int* ei = (const int*)eiv;
        s = ei[e];
        d = ei[Ee + e];
    }
    s = min(max(s, 0), Nn - 1);
    d = min(max(d, 0), Nn - 1);
    g_src[e] = s;
    g_dst[e] = d;
    atomicAdd(&g_degi[d], 1);
}

__global__ void k_prep_nodes() {
    int i = blockIdx.x * blockDim.x + threadIdx.x;
    if (i >= Nn) return;
    float d = (float)g_degi[i] + 1.0f;
    g_dinv[i] = 1.0f / d;
    g_dis[i]  = rsqrtf(d);
}

// ------------------------- exclusive scan of degrees (single block) ----------
__global__ void k_scan() {
    const int T = 1024;
    const int CHUNK = (Nn + T - 1) / T;     // 196
    __shared__ int bs[T];
    int t = threadIdx.x;
    int lo = t * CHUNK, hi = min(lo + CHUNK, Nn);
    int s = 0;
    for (int i = lo; i < hi; i++) s += g_degi[i];
    bs[t] = s;
    __syncthreads();
    // Hillis-Steele inclusive scan over 1024 partials
    for (int o = 1; o < T; o <<= 1) {
        int v = (t >= o) ? bs[t - o] : 0;
        __syncthreads();
        bs[t] += v;
        __syncthreads();
    }
    int run = (t > 0) ? bs[t - 1] : 0;      // exclusive prefix for this chunk
    for (int i = lo; i < hi; i++) {
        g_rowptr[i] = run;
        g_cursor[i] = run;
        run += g_degi[i];
    }
    if (t == T - 1) g_rowptr[Nn] = bs[T - 1];
}

// ------------------------- counting-sort edges into CSR ----------------------
__global__ void k_sort() {
    int e = blockIdx.x * blockDim.x + threadIdx.x;
    if (e >= Ee) return;
    int s = g_src[e], d = g_dst[e];
    float w = g_dis[s] * g_dis[d];
    int pos = atomicAdd(&g_cursor[d], 1);
    g_edge[pos] = make_int2(s, __float_as_int(w));
}

// ------------------------- layer 1 matmul (128 -> 32) -------------------------
__global__ void k_mm1(const float* __restrict__ x,
                      const float* __restrict__ W1) {
    __shared__ float Ws[INC * C];
    for (int t = threadIdx.x; t < INC * C; t += blockDim.x) Ws[t] = W1[t];
    __syncthreads();
    int warp = threadIdx.x >> 5, lane = threadIdx.x & 31;
    int i = blockIdx.x * 8 + warp;
    if (i >= Nn) return;
    float xr[4];
#pragma unroll
    for (int j = 0; j < 4; j++) xr[j] = x[i * INC + j * 32 + lane];
    float acc = 0.f;
#pragma unroll
    for (int k = 0; k < INC; k++) {
        float xk = __shfl_sync(0xffffffffu, xr[k >> 5], k & 31);
        acc = fmaf(xk, Ws[k * C + lane], acc);
    }
    g_h[i * C + lane] = acc;
}

// ------------------------- CSR gather (the hot kernel, no atomics) -----------
// warp per node; lane = channel; self-loop + bias folded in
__global__ void k_gather(int sel, const float* __restrict__ b) {
    float* __restrict__ agg = (float*)selbuf(sel);
    const float* __restrict__ h = g_h;
    int lane = threadIdx.x & 31;
    int i = blockIdx.x * (blockDim.x >> 5) + (threadIdx.x >> 5);
    if (i >= Nn) return;
    int e  = g_rowptr[i];
    int e1 = g_rowptr[i + 1];
    float acc = h[i * C + lane] * g_dinv[i] + b[lane];
    for (; e + 4 <= e1; e += 4) {
        int2 p0 = g_edge[e + 0];
        int2 p1 = g_edge[e + 1];
        int2 p2 = g_edge[e + 2];
        int2 p3 = g_edge[e + 3];
        float v0 = h[p0.x * C + lane] * __int_as_float(p0.y);
        float v1 = h[p1.x * C + lane] * __int_as_float(p1.y);
        float v2 = h[p2.x * C + lane] * __int_as_float(p2.y);
        float v3 = h[p3.x * C + lane] * __int_as_float(p3.y);
        acc += (v0 + v1) + (v2 + v3);
    }
    for (; e < e1; e++) {
        int2 p = g_edge[e];
        acc += h[p.x * C + lane] * __int_as_float(p.y);
    }
    agg[i * C + lane] = acc;
}

// ------------------------- BN stats: per-block fp32 partials -------------------------
__global__ void k_stats(int sel, int n, int pass) {
    const float* __restrict__ a = selbuf(sel);
    int lane = threadIdx.x & 31, warp = threadIdx.x >> 5;
    int nwt = gridDim.x * 8;
    float s = 0.f, q = 0.f;
    for (int i = blockIdx.x * 8 + warp; i < n; i += nwt) {
        float v = a[i * C + lane];
        s += v;
        q += v * v;
    }
    __shared__ float ss[8][32], sq[8][32];
    ss[warp][lane] = s;
    sq[warp][lane] = q;
    __syncthreads();
    if (warp == 0) {
        float S = 0.f, Q = 0.f;
#pragma unroll
        for (int w = 0; w < 8; w++) { S += ss[w][lane]; Q += sq[w][lane]; }
        g_part[pass * (SBLK * 64) + blockIdx.x * 64 + lane]      = S;
        g_part[pass * (SBLK * 64) + blockIdx.x * 64 + 32 + lane] = Q;
    }
}

// finalize: sum partials (fp64 registers only), emit scale/shift per channel
__global__ void k_finalize(int pass, int nb, float n,
                           const float* __restrict__ gamma,
                           const float* __restrict__ beta) {
    int c = threadIdx.x;   // 32 threads
    double S = 0.0, Q = 0.0;
    const float* p = &g_part[pass * (SBLK * 64)];
    for (int b = 0; b < nb; b++) {
        S += (double)p[b * 64 + c];
        Q += (double)p[b * 64 + 32 + c];
    }
    double m   = S / (double)n;
    double var = Q / (double)n - m * m;
    if (var < 0.0) var = 0.0;
    float r  = rsqrtf((float)var + EPSF);
    float sc = r * gamma[c];
    g_bnco[pass * 64 + c]      = sc;
    g_bnco[pass * 64 + 32 + c] = beta[c] - (float)m * sc;
}

// ------------------------- fused BN-apply + ReLU + matmul (32->32) ----------
__global__ void k_mm_small(int selIn, int pass,
                           const float* __restrict__ W) {
    const float* __restrict__ ain = selbuf(selIn);
    __shared__ float Ws[C * C];
    for (int t = threadIdx.x; t < C * C; t += blockDim.x) Ws[t] = W[t];
    __syncthreads();
    int warp = threadIdx.x >> 5, lane = threadIdx.x & 31;
    int i = blockIdx.x * 8 + warp;
    if (i >= Nn) return;
    float sc = g_bnco[pass * 64 + lane];
    float sh = g_bnco[pass * 64 + 32 + lane];
    float a = ain[i * C + lane];
    float z = fmaxf(a * sc + sh, 0.f);
    float acc = 0.f;
#pragma unroll
    for (int k = 0; k < C; k++) {
        float zk = __shfl_sync(0xffffffffu, z, k);
        acc = fmaf(zk, Ws[k * C + lane], acc);
    }
    g_h[i * C + lane] = acc;
}

// ------------------------- pooling: sum nodes into graphs -------------------------
__global__ void k_pool(const void* __restrict__ batchv) {
    int lane = threadIdx.x & 31;
    int i = blockIdx.x * (blockDim.x >> 5) + (threadIdx.x >> 5);
    if (i >= Nn) return;
    int b;
    if (g_is64) b = (int)((const long long*)batchv)[i];
    else        b = ((const int*)batchv)[i];
    b = min(max(b, 0), Gg - 1);
    atomicAdd(&g_pool[b * C + lane], g_aggA[i * C + lane]);
}

// ------------------------- MLP head -------------------------
__global__ void k_mlp_mm1(const float* __restrict__ M1, const float* __restrict__ mb1) {
    __shared__ float Ws[C * C];
    for (int t = threadIdx.x; t < C * C; t += blockDim.x) Ws[t] = M1[t];
    __syncthreads();
    int warp = threadIdx.x >> 5, lane = threadIdx.x & 31;
    int g = blockIdx.x * 8 + warp;
    if (g >= Gg) return;
    float z = g_pool[g * C + lane];
    float acc = mb1[lane];
#pragma unroll
    for (int k = 0; k < C; k++) {
        float zk = __shfl_sync(0xffffffffu, z, k);
        acc = fmaf(zk, Ws[k * C + lane], acc);
    }
    g_mlpA[g * C + lane] = acc;
}

__global__ void k_mlp_mm2(const float* __restrict__ M2, const float* __restrict__ mb2) {
    __shared__ float Ws[C * C];
    for (int t = threadIdx.x; t < C * C; t += blockDim.x) Ws[t] = M2[t];
    __syncthreads();
    int warp = threadIdx.x >> 5, lane = threadIdx.x & 31;
    int g = blockIdx.x * 8 + warp;
    if (g >= Gg) return;
    float sc = g_bnco[2 * 64 + lane];
    float sh = g_bnco[2 * 64 + 32 + lane];
    float a = g_mlpA[g * C + lane];
    float z = fmaxf(a * sc + sh, 0.f);
    float acc = mb2[lane];
#pragma unroll
    for (int k = 0; k < C; k++) {
        float zk = __shfl_sync(0xffffffffu, z, k);
        acc = fmaf(zk, Ws[k * C + lane], acc);
    }
    g_mlpB[g * C + lane] = acc;
}

__global__ void k_mlp_out(const float* __restrict__ M3, const float* __restrict__ mb3,
                          float* __restrict__ out) {
    int lane = threadIdx.x & 31;
    int g = blockIdx.x * (blockDim.x >> 5) + (threadIdx.x >> 5);
    if (g >= Gg) return;
    float sc = g_bnco[3 * 64 + lane];
    float sh = g_bnco[3 * 64 + 32 + lane];
    float v  = g_mlpB[g * C + lane];
    float z  = fmaxf(v * sc + sh, 0.f);
    float t  = z * M3[lane];
#pragma unroll
    for (int o = 16; o; o >>= 1) t += __shfl_down_sync(0xffffffffu, t, o);
    if (lane == 0) out[g] = t + mb3[0];
}

// ------------------------- launch -------------------------
extern "C" void kernel_launch(void* const* d_in, const int* in_sizes, int n_in,
                              void* d_out, int out_size) {
    (void)in_sizes; (void)n_in; (void)out_size;
    const float* x     = (const float*)d_in[0];
    const void*  ei    = d_in[1];
    const void*  batch = d_in[2];
    const float* W1  = (const float*)d_in[3];
    const float* b1  = (const float*)d_in[4];
    const float* gm1 = (const float*)d_in[5];
    const float* be1 = (const float*)d_in[6];
    const float* W2  = (const float*)d_in[7];
    const float* b2  = (const float*)d_in[8];
    const float* gm2 = (const float*)d_in[9];
    const float* be2 = (const float*)d_in[10];
    const float* W3  = (const float*)d_in[11];
    const float* b3  = (const float*)d_in[12];
    const float* M1  = (const float*)d_in[13];
    const float* mb1 = (const float*)d_in[14];
    const float* mg1 = (const float*)d_in[15];
    const float* mbe1= (const float*)d_in[16];
    const float* M2  = (const float*)d_in[17];
    const float* mb2 = (const float*)d_in[18];
    const float* mg2 = (const float*)d_in[19];
    const float* mbe2= (const float*)d_in[20];
    const float* M3  = (const float*)d_in[21];
    const float* mb3 = (const float*)d_in[22];
    float* out = (float*)d_out;

    const int TB = 256;
    k_detect<<<1, 32>>>((const unsigned int*)ei);
    k_zero<<<800, TB>>>();
    k_prep_edges<<<(Ee + TB - 1) / TB, TB>>>(ei);
    k_prep_nodes<<<(Nn + TB - 1) / TB, TB>>>();
    k_scan<<<1, 1024>>>();
    k_sort<<<(Ee + TB - 1) / TB, TB>>>();

    // layer 1: conv(x) -> aggA
    k_mm1<<<Nn / 8, TB>>>(x, W1);
    k_gather<<<Nn / 8, TB>>>(0, b1);
    k_stats<<<SBLK, TB>>>(0, Nn, 0);
    k_finalize<<<1, 32>>>(0, SBLK, (float)Nn, gm1, be1);

    // layer 2: relu(bn(aggA)) @ W2 -> aggB
    k_mm_small<<<Nn / 8, TB>>>(0, 0, W2);
    k_gather<<<Nn / 8, TB>>>(1, b2);
    k_stats<<<SBLK, TB>>>(1, Nn, 1);
    k_finalize<<<1, 32>>>(1, SBLK, (float)Nn, gm2, be2);

    // layer 3: relu(bn(aggB)) @ W3 -> aggA (no bn after)
    k_mm_small<<<Nn / 8, TB>>>(1, 1, W3);
    k_gather<<<Nn / 8, TB>>>(0, b3);

    // pool + MLP head
    k_pool<<<Nn / 8, TB>>>(batch);
    k_mlp_mm1<<<Gg / 8, TB>>>(M1, mb1);
    k_stats<<<SBLK_G, TB>>>(2, Gg, 2);
    k_finalize<<<1, 32>>>(2, SBLK_G, (float)Gg, mg1, mbe1);
    k_mlp_mm2<<<Gg / 8, TB>>>(M2, mb2);
    k_stats<<<SBLK_G, TB>>>(3, Gg, 3);
    k_finalize<<<1, 32>>>(3, SBLK_G, (float)Gg, mg2, mbe2);
    k_mlp_out<<<Gg / 8, TB>>>(M3, mb3, out);
}

// round 5
// speedup vs baseline: 1.3827x; 1.3782x over previous
#include <cuda_runtime.h>

#define Nn 200000
#define Ee 6400000
#define Gg 1024
#define C  32
#define INC 128
#define EPSF 1e-5f
#define SBLK 128          // blocks for node-level BN stats
#define SBLK_G 8          // blocks for graph-level BN stats
#define SCB 256           // nodes per scan block
#define NSB ((Nn + SCB - 1) / SCB)   // 782 scan blocks

// ------------------------- scratch (device globals) -------------------------
__device__ int    g_src[Ee];
__device__ int    g_dst[Ee];
__device__ int2   g_edge[Ee];         // CSR-sorted {src, w(bits)} per dst
__device__ int    g_degi[Nn];
__device__ int    g_rowptr[Nn + 1];
__device__ int    g_cursor[Nn];
__device__ int    g_bsum[NSB];
__device__ int    g_boff[NSB];
__device__ float  g_dis[Nn];
__device__ float  g_dinv[Nn];
__device__ float  g_h[Nn * C];        // transformed features (gather source)
__device__ float  g_aggA[Nn * C];
__device__ float  g_aggB[Nn * C];
__device__ float  g_mlpA[Gg * C];
__device__ float  g_mlpB[Gg * C];
__device__ float  g_pool[Gg * C];
__device__ float  g_part[4 * SBLK * 64];  // per-pass, per-block {sum[32], sumsq[32]}
__device__ float  g_bnco[4 * 64];         // per-pass {scale[32], shift[32]}
__device__ int    g_is64;                 // 1 if index inputs are int64, 0 if int32

__device__ __forceinline__ const float* selbuf(int s) {
    if (s == 0) return g_aggA;
    if (s == 1) return g_aggB;
    if (s == 2) return g_mlpA;
    return g_mlpB;
}

// ------------------------- init: dtype detect (block 0) + zeroing (all) -----
__global__ void k_init(const unsigned int* __restrict__ w) {
    if (blockIdx.x == 0 && threadIdx.x < 32) {
        unsigned int acc = 0;
        for (int i = threadIdx.x; i < 2048; i += 32)
            if (i & 1) acc |= w[i];
#pragma unroll
        for (int o = 16; o; o >>= 1) acc |= __shfl_down_sync(0xffffffffu, acc, o);
        if (threadIdx.x == 0) g_is64 = (acc == 0u) ? 1 : 0;
    }
    int idx = blockIdx.x * blockDim.x + threadIdx.x;
    int stride = gridDim.x * blockDim.x;
    for (int i = idx; i < Nn; i += stride)      g_degi[i] = 0;
    for (int i = idx; i < Gg * C; i += stride)  g_pool[i] = 0.f;
}

// convert indices -> clamped int32, count in-degree
__global__ void k_prep_edges(const void* __restrict__ eiv) {
    int e = blockIdx.x * blockDim.x + threadIdx.x;
    if (e >= Ee) return;
    int s, d;
    if (g_is64) {
        const long long* ei = (const long long*)eiv;
        s = (int)ei[e];
        d = (int)ei[Ee + e];
    } else {
        const int* ei = (const int*)eiv;
        s = ei[e];
        d = ei[Ee + e];
    }
    s = min(max(s, 0), Nn - 1);
    d = min(max(d, 0), Nn - 1);
    g_src[e] = s;
    g_dst[e] = d;
    atomicAdd(&g_degi[d], 1);
}

// ------------------------- multi-block exclusive scan ------------------------
// phase 1: per-block degree sums (coalesced)
__global__ void k_scan1() {
    __shared__ int sh[SCB / 32];
    int t = threadIdx.x;
    int i = blockIdx.x * SCB + t;
    int v = (i < Nn) ? g_degi[i] : 0;
#pragma unroll
    for (int o = 16; o; o >>= 1) v += __shfl_down_sync(0xffffffffu, v, o);
    if ((t & 31) == 0) sh[t >> 5] = v;
    __syncthreads();
    if (t < SCB / 32) {
        int s = sh[t];
#pragma unroll
        for (int o = SCB / 64; o; o >>= 1) s += __shfl_down_sync(0xffffffffu, s, o);
        if (t == 0) g_bsum[blockIdx.x] = s;
    }
}

// phase 2: single block scans the 782 block sums -> exclusive offsets
__global__ void k_scan2() {
    __shared__ int bs[1024];
    int t = threadIdx.x;
    int v = (t < NSB) ? g_bsum[t] : 0;
    bs[t] = v;
    __syncthreads();
    for (int o = 1; o < 1024; o <<= 1) {
        int u = (t >= o) ? bs[t - o] : 0;
        __syncthreads();
        bs[t] += u;
        __syncthreads();
    }
    if (t < NSB) g_boff[t] = bs[t] - v;          // exclusive
    if (t == NSB - 1) g_rowptr[Nn] = bs[t];      // total edge count
}

// phase 3: per-block intra scan -> rowptr/cursor; also dinv/dis
__global__ void k_scan3() {
    __shared__ int sh[SCB];
    int t = threadIdx.x;
    int i = blockIdx.x * SCB + t;
    int deg = (i < Nn) ? g_degi[i] : 0;
    sh[t] = deg;
    __syncthreads();
    int incl = deg;
    for (int o = 1; o < SCB; o <<= 1) {
        int u = (t >= o) ? sh[t - o] : 0;
        __syncthreads();
        incl += u;
        sh[t] = incl;
        __syncthreads();
    }
    if (i < Nn) {
        int off = g_boff[blockIdx.x] + incl - deg;
        g_rowptr[i] = off;
        g_cursor[i] = off;
        float d = (float)deg + 1.0f;
        g_dinv[i] = 1.0f / d;
        g_dis[i]  = rsqrtf(d);
    }
}

// ------------------------- counting-sort edges into CSR ----------------------
__global__ void k_sort() {
    int e = blockIdx.x * blockDim.x + threadIdx.x;
    if (e >= Ee) return;
    int s = g_src[e], d = g_dst[e];
    float w = g_dis[s] * g_dis[d];
    int pos = atomicAdd(&g_cursor[d], 1);
    g_edge[pos] = make_int2(s, __float_as_int(w));
}

// ------------------------- layer 1 matmul (128 -> 32) -------------------------
__global__ void k_mm1(const float* __restrict__ x,
                      const float* __restrict__ W1) {
    __shared__ float Ws[INC * C];
    for (int t = threadIdx.x; t < INC * C; t += blockDim.x) Ws[t] = W1[t];
    __syncthreads();
    int warp = threadIdx.x >> 5, lane = threadIdx.x & 31;
    int i = blockIdx.x * 8 + warp;
    if (i >= Nn) return;
    float xr[4];
#pragma unroll
    for (int j = 0; j < 4; j++) xr[j] = x[i * INC + j * 32 + lane];
    float acc = 0.f;
#pragma unroll
    for (int k = 0; k < INC; k++) {
        float xk = __shfl_sync(0xffffffffu, xr[k >> 5], k & 31);
        acc = fmaf(xk, Ws[k * C + lane], acc);
    }
    g_h[i * C + lane] = acc;
}

// ------------------------- CSR gather (the hot kernel, no atomics) -----------
// warp per node; lane = channel; self-loop + bias folded in; 8-wide unroll
__global__ void k_gather(int sel, const float* __restrict__ b) {
    float* __restrict__ agg = (float*)selbuf(sel);
    const float* __restrict__ h = g_h;
    int lane = threadIdx.x & 31;
    int i = blockIdx.x * (blockDim.x >> 5) + (threadIdx.x >> 5);
    if (i >= Nn) return;
    int e  = g_rowptr[i];
    int e1 = g_rowptr[i + 1];
    float acc = h[i * C + lane] * g_dinv[i] + b[lane];
    for (; e + 8 <= e1; e += 8) {
        int2 p0 = g_edge[e + 0];
        int2 p1 = g_edge[e + 1];
        int2 p2 = g_edge[e + 2];
        int2 p3 = g_edge[e + 3];
        int2 p4 = g_edge[e + 4];
        int2 p5 = g_edge[e + 5];
        int2 p6 = g_edge[e + 6];
        int2 p7 = g_edge[e + 7];
        float v0 = h[p0.x * C + lane] * __int_as_float(p0.y);
        float v1 = h[p1.x * C + lane] * __int_as_float(p1.y);
        float v2 = h[p2.x * C + lane] * __int_as_float(p2.y);
        float v3 = h[p3.x * C + lane] * __int_as_float(p3.y);
        float v4 = h[p4.x * C + lane] * __int_as_float(p4.y);
        float v5 = h[p5.x * C + lane] * __int_as_float(p5.y);
        float v6 = h[p6.x * C + lane] * __int_as_float(p6.y);
        float v7 = h[p7.x * C + lane] * __int_as_float(p7.y);
        acc += ((v0 + v1) + (v2 + v3)) + ((v4 + v5) + (v6 + v7));
    }
    for (; e < e1; e++) {
        int2 p = g_edge[e];
        acc += h[p.x * C + lane] * __int_as_float(p.y);
    }
    agg[i * C + lane] = acc;
}

// ------------------------- BN stats: per-block fp32 partials ------------------
__global__ void k_stats(int sel, int n, int pass) {
    const float* __restrict__ a = selbuf(sel);
    int lane = threadIdx.x & 31, warp = threadIdx.x >> 5;
    int nwt = gridDim.x * 8;
    float s = 0.f, q = 0.f;
    for (int i = blockIdx.x * 8 + warp; i < n; i += nwt) {
        float v = a[i * C + lane];
        s += v;
        q += v * v;
    }
    __shared__ float ss[8][32], sq[8][32];
    ss[warp][lane] = s;
    sq[warp][lane] = q;
    __syncthreads();
    if (warp == 0) {
        float S = 0.f, Q = 0.f;
#pragma unroll
        for (int w = 0; w < 8; w++) { S += ss[w][lane]; Q += sq[w][lane]; }
        g_part[pass * (SBLK * 64) + blockIdx.x * 64 + lane]      = S;
        g_part[pass * (SBLK * 64) + blockIdx.x * 64 + 32 + lane] = Q;
    }
}

// finalize: sum partials (fp64 registers only), emit scale/shift per channel
__global__ void k_finalize(int pass, int nb, float n,
                           const float* __restrict__ gamma,
                           const float* __restrict__ beta) {
    int c = threadIdx.x;   // 32 threads
    double S = 0.0, Q = 0.0;
    const float* p = &g_part[pass * (SBLK * 64)];
    for (int b = 0; b < nb; b++) {
        S += (double)p[b * 64 + c];
        Q += (double)p[b * 64 + 32 + c];
    }
    double m   = S / (double)n;
    double var = Q / (double)n - m * m;
    if (var < 0.0) var = 0.0;
    float r  = rsqrtf((float)var + EPSF);
    float sc = r * gamma[c];
    g_bnco[pass * 64 + c]      = sc;
    g_bnco[pass * 64 + 32 + c] = beta[c] - (float)m * sc;
}

// ------------------------- fused BN-apply + ReLU + matmul (32->32) ----------
__global__ void k_mm_small(int selIn, int pass,
                           const float* __restrict__ W) {
    const float* __restrict__ ain = selbuf(selIn);
    __shared__ float Ws[C * C];
    for (int t = threadIdx.x; t < C * C; t += blockDim.x) Ws[t] = W[t];
    __syncthreads();
    int warp = threadIdx.x >> 5, lane = threadIdx.x & 31;
    int i = blockIdx.x * 8 + warp;
    if (i >= Nn) return;
    float sc = g_bnco[pass * 64 + lane];
    float sh = g_bnco[pass * 64 + 32 + lane];
    float a = ain[i * C + lane];
    float z = fmaxf(a * sc + sh, 0.f);
    float acc = 0.f;
#pragma unroll
    for (int k = 0; k < C; k++) {
        float zk = __shfl_sync(0xffffffffu, z, k);
        acc = fmaf(zk, Ws[k * C + lane], acc);
    }
    g_h[i * C + lane] = acc;
}

// ------------------------- pooling: sum nodes into graphs --------------------
__global__ void k_pool(const void* __restrict__ batchv) {
    int lane = threadIdx.x & 31;
    int i = blockIdx.x * (blockDim.x >> 5) + (threadIdx.x >> 5);
    if (i >= Nn) return;
    int b;
    if (g_is64) b = (int)((const long long*)batchv)[i];
    else        b = ((const int*)batchv)[i];
    b = min(max(b, 0), Gg - 1);
    atomicAdd(&g_pool[b * C + lane], g_aggA[i * C + lane]);
}

// ------------------------- MLP head -------------------------
__global__ void k_mlp_mm1(const float* __restrict__ M1, const float* __restrict__ mb1) {
    __shared__ float Ws[C * C];
    for (int t = threadIdx.x; t < C * C; t += blockDim.x) Ws[t] = M1[t];
    __syncthreads();
    int warp = threadIdx.x >> 5, lane = threadIdx.x & 31;
    int g = blockIdx.x * 8 + warp;
    if (g >= Gg) return;
    float z = g_pool[g * C + lane];
    float acc = mb1[lane];
#pragma unroll
    for (int k = 0; k < C; k++) {
        float zk = __shfl_sync(0xffffffffu, z, k);
        acc = fmaf(zk, Ws[k * C + lane], acc);
    }
    g_mlpA[g * C + lane] = acc;
}

__global__ void k_mlp_mm2(const float* __restrict__ M2, const float* __restrict__ mb2) {
    __shared__ float Ws[C * C];
    for (int t = threadIdx.x; t < C * C; t += blockDim.x) Ws[t] = M2[t];
    __syncthreads();
    int warp = threadIdx.x >> 5, lane = threadIdx.x & 31;
    int g = blockIdx.x * 8 + warp;
    if (g >= Gg) return;
    float sc = g_bnco[2 * 64 + lane];
    float sh = g_bnco[2 * 64 + 32 + lane];
    float a = g_mlpA[g * C + lane];
    float z = fmaxf(a * sc + sh, 0.f);
    float acc = mb2[lane];
#pragma unroll
    for (int k = 0; k < C; k++) {
        float zk = __shfl_sync(0xffffffffu, z, k);
        acc = fmaf(zk, Ws[k * C + lane], acc);
    }
    g_mlpB[g * C + lane] = acc;
}

__global__ void k_mlp_out(const float* __restrict__ M3, const float* __restrict__ mb3,
                          float* __restrict__ out) {
    int lane = threadIdx.x & 31;
    int g = blockIdx.x * (blockDim.x >> 5) + (threadIdx.x >> 5);
    if (g >= Gg) return;
    float sc = g_bnco[3 * 64 + lane];
    float sh = g_bnco[3 * 64 + 32 + lane];
    float v  = g_mlpB[g * C + lane];
    float z  = fmaxf(v * sc + sh, 0.f);
    float t  = z * M3[lane];
#pragma unroll
    for (int o = 16; o; o >>= 1) t += __shfl_down_sync(0xffffffffu, t, o);
    if (lane == 0) out[g] = t + mb3[0];
}

// ------------------------- launch -------------------------
extern "C" void kernel_launch(void* const* d_in, const int* in_sizes, int n_in,
                              void* d_out, int out_size) {
    (void)in_sizes; (void)n_in; (void)out_size;
    const float* x     = (const float*)d_in[0];
    const void*  ei    = d_in[1];
    const void*  batch = d_in[2];
    const float* W1  = (const float*)d_in[3];
    const float* b1  = (const float*)d_in[4];
    const float* gm1 = (const float*)d_in[5];
    const float* be1 = (const float*)d_in[6];
    const float* W2  = (const float*)d_in[7];
    const float* b2  = (const float*)d_in[8];
    const float* gm2 = (const float*)d_in[9];
    const float* be2 = (const float*)d_in[10];
    const float* W3  = (const float*)d_in[11];
    const float* b3  = (const float*)d_in[12];
    const float* M1  = (const float*)d_in[13];
    const float* mb1 = (const float*)d_in[14];
    const float* mg1 = (const float*)d_in[15];
    const float* mbe1= (const float*)d_in[16];
    const float* M2  = (const float*)d_in[17];
    const float* mb2 = (const float*)d_in[18];
    const float* mg2 = (const float*)d_in[19];
    const float* mbe2= (const float*)d_in[20];
    const float* M3  = (const float*)d_in[21];
    const float* mb3 = (const float*)d_in[22];
    float* out = (float*)d_out;

    const int TB = 256;
    k_init<<<800, TB>>>((const unsigned int*)ei);          // 0
    k_prep_edges<<<(Ee + TB - 1) / TB, TB>>>(ei);          // 1
    k_scan1<<<NSB, SCB>>>();                               // 2
    k_mm1<<<Nn / 8, TB>>>(x, W1);                          // 3 (ncu capture target)
    k_scan2<<<1, 1024>>>();                                // 4
    k_scan3<<<NSB, SCB>>>();                               // 5
    k_sort<<<(Ee + TB - 1) / TB, TB>>>();                  // 6

    // layer 1: conv(x) -> aggA
    k_gather<<<Nn / 8, TB>>>(0, b1);
    k_stats<<<SBLK, TB>>>(0, Nn, 0);
    k_finalize<<<1, 32>>>(0, SBLK, (float)Nn, gm1, be1);

    // layer 2: relu(bn(aggA)) @ W2 -> aggB
    k_mm_small<<<Nn / 8, TB>>>(0, 0, W2);
    k_gather<<<Nn / 8, TB>>>(1, b2);
    k_stats<<<SBLK, TB>>>(1, Nn, 1);
    k_finalize<<<1, 32>>>(1, SBLK, (float)Nn, gm2, be2);

    // layer 3: relu(bn(aggB)) @ W3 -> aggA (no bn after)
    k_mm_small<<<Nn / 8, TB>>>(1, 1, W3);
    k_gather<<<Nn / 8, TB>>>(0, b3);

    // pool + MLP head
    k_pool<<<Nn / 8, TB>>>(batch);
    k_mlp_mm1<<<Gg / 8, TB>>>(M1, mb1);
    k_stats<<<SBLK_G, TB>>>(2, Gg, 2);
    k_finalize<<<1, 32>>>(2, SBLK_G, (float)Gg, mg1, mbe1);
    k_mlp_mm2<<<Gg / 8, TB>>>(M2, mb2);
    k_stats<<<SBLK_G, TB>>>(3, Gg, 3);
    k_finalize<<<1, 32>>>(3, SBLK_G, (float)Gg, mg2, mbe2);
    k_mlp_out<<<Gg / 8, TB>>>(M3, mb3, out);
}

// round 8
// speedup vs baseline: 1.7241x; 1.2469x over previous
#include <cuda_runtime.h>

#define Nn 200000
#define Ee 6400000
#define Gg 1024
#define C  32
#define INC 128
#define EPSF 1e-5f
#define SBLK 128          // blocks for node-level BN stats
#define SBLK_G 8          // blocks for graph-level BN stats
#define SCB 256           // nodes per scan block
#define NSB ((Nn + SCB - 1) / SCB)   // 782 scan blocks

// ------------------------- scratch (device globals) -------------------------
__device__ int    g_src[Ee];
__device__ int    g_dst[Ee];
__device__ int2   g_edge[Ee];         // CSR-sorted {src, w(bits)} per dst
__device__ int    g_degi[Nn];
__device__ int    g_rowptr[Nn + 1];
__device__ int    g_cursor[Nn];
__device__ int    g_bsum[NSB];
__device__ int    g_boff[NSB];
__device__ float  g_dis[Nn];
__device__ float  g_dinv[Nn];
__device__ float  g_h[Nn * C];        // transformed features (gather source)
__device__ float  g_aggA[Nn * C];
__device__ float  g_aggB[Nn * C];
__device__ float  g_mlpA[Gg * C];
__device__ float  g_mlpB[Gg * C];
__device__ float  g_pool[Gg * C];
__device__ float  g_part[4 * SBLK * 64];  // per-pass, per-block {sum[32], sumsq[32]}
__device__ float  g_bnco[4 * 64];         // per-pass {scale[32], shift[32]}
__device__ int    g_is64;                 // 1 if index inputs are int64, 0 if int32

__device__ __forceinline__ const float* selbuf(int s) {
    if (s == 0) return g_aggA;
    if (s == 1) return g_aggB;
    if (s == 2) return g_mlpA;
    return g_mlpB;
}

// ------------------------- init: dtype detect (block 0) + zeroing (all) -----
__global__ void k_init(const unsigned int* __restrict__ w) {
    if (blockIdx.x == 0 && threadIdx.x < 32) {
        unsigned int acc = 0;
        for (int i = threadIdx.x; i < 2048; i += 32)
            if (i & 1) acc |= w[i];
#pragma unroll
        for (int o = 16; o; o >>= 1) acc |= __shfl_down_sync(0xffffffffu, acc, o);
        if (threadIdx.x == 0) g_is64 = (acc == 0u) ? 1 : 0;
    }
    int idx = blockIdx.x * blockDim.x + threadIdx.x;
    int stride = gridDim.x * blockDim.x;
    for (int i = idx; i < Nn; i += stride)      g_degi[i] = 0;
    for (int i = idx; i < Gg * C; i += stride)  g_pool[i] = 0.f;
}

// convert indices -> clamped int32, count in-degree
__global__ void k_prep_edges(const void* __restrict__ eiv) {
    int e = blockIdx.x * blockDim.x + threadIdx.x;
    if (e >= Ee) return;
    int s, d;
    if (g_is64) {
        const long long* ei = (const long long*)eiv;
        s = (int)ei[e];
        d = (int)ei[Ee + e];
    } else {
        const int* ei = (const int*)eiv;
        s = ei[e];
        d = ei[Ee + e];
    }
    s = min(max(s, 0), Nn - 1);
    d = min(max(d, 0), Nn - 1);
    g_src[e] = s;
    g_dst[e] = d;
    atomicAdd(&g_degi[d], 1);
}

// ------------------------- multi-block exclusive scan ------------------------
__global__ void k_scan1() {
    __shared__ int sh[SCB / 32];
    int t = threadIdx.x;
    int i = blockIdx.x * SCB + t;
    int v = (i < Nn) ? g_degi[i] : 0;
#pragma unroll
    for (int o = 16; o; o >>= 1) v += __shfl_down_sync(0xffffffffu, v, o);
    if ((t & 31) == 0) sh[t >> 5] = v;
    __syncthreads();
    if (t < SCB / 32) {
        int s = sh[t];
#pragma unroll
        for (int o = SCB / 64; o; o >>= 1) s += __shfl_down_sync(0xffffffffu, s, o);
        if (t == 0) g_bsum[blockIdx.x] = s;
    }
}

__global__ void k_scan2() {
    __shared__ int bs[1024];
    int t = threadIdx.x;
    int v = (t < NSB) ? g_bsum[t] : 0;
    bs[t] = v;
    __syncthreads();
    for (int o = 1; o < 1024; o <<= 1) {
        int u = (t >= o) ? bs[t - o] : 0;
        __syncthreads();
        bs[t] += u;
        __syncthreads();
    }
    if (t < NSB) g_boff[t] = bs[t] - v;          // exclusive
    if (t == NSB - 1) g_rowptr[Nn] = bs[t];      // total edge count
}

__global__ void k_scan3() {
    __shared__ int sh[SCB];
    int t = threadIdx.x;
    int i = blockIdx.x * SCB + t;
    int deg = (i < Nn) ? g_degi[i] : 0;
    sh[t] = deg;
    __syncthreads();
    int incl = deg;
    for (int o = 1; o < SCB; o <<= 1) {
        int u = (t >= o) ? sh[t - o] : 0;
        __syncthreads();
        incl += u;
        sh[t] = incl;
        __syncthreads();
    }
    if (i < Nn) {
        int off = g_boff[blockIdx.x] + incl - deg;
        g_rowptr[i] = off;
        g_cursor[i] = off;
        float d = (float)deg + 1.0f;
        g_dinv[i] = 1.0f / d;
        g_dis[i]  = rsqrtf(d);
    }
}

// ------------------------- counting-sort edges into CSR ----------------------
__global__ void k_sort() {
    int e = blockIdx.x * blockDim.x + threadIdx.x;
    if (e >= Ee) return;
    int s = g_src[e], d = g_dst[e];
    float w = g_dis[s] * g_dis[d];
    int pos = atomicAdd(&g_cursor[d], 1);
    g_edge[pos] = make_int2(s, __float_as_int(w));
}

// ------------------------- layer 1 matmul (128 -> 32), register-blocked ------
// block = 256 threads, 64 nodes; warp computes 8 nodes x 32 channels
__global__ void k_mm1(const float* __restrict__ x,
                      const float* __restrict__ W1) {
    __shared__ float Xs[64 * INC];
    __shared__ float Ws[INC * C];
    int t = threadIdx.x;
    int base = blockIdx.x * 64;
    {
        const float4* x4 = (const float4*)(x + (size_t)base * INC);
        float4* Xs4 = (float4*)Xs;
        for (int i = t; i < 64 * INC / 4; i += 256) Xs4[i] = x4[i];
        const float4* w4 = (const float4*)W1;
        float4* Ws4 = (float4*)Ws;
        for (int i = t; i < INC * C / 4; i += 256) Ws4[i] = w4[i];
    }
    __syncthreads();
    int warp = t >> 5, lane = t & 31;
    float acc[8] = {0.f, 0.f, 0.f, 0.f, 0.f, 0.f, 0.f, 0.f};
    const float* xw = Xs + warp * 8 * INC;
#pragma unroll 4
    for (int k4 = 0; k4 < INC / 4; k4++) {
        float w0 = Ws[(k4 * 4 + 0) * C + lane];
        float w1 = Ws[(k4 * 4 + 1) * C + lane];
        float w2 = Ws[(k4 * 4 + 2) * C + lane];
        float w3 = Ws[(k4 * 4 + 3) * C + lane];
#pragma unroll
        for (int n = 0; n < 8; n++) {
            float4 xv = ((const float4*)(xw + n * INC))[k4];
            acc[n] = fmaf(xv.x, w0, acc[n]);
            acc[n] = fmaf(xv.y, w1, acc[n]);
            acc[n] = fmaf(xv.z, w2, acc[n]);
            acc[n] = fmaf(xv.w, w3, acc[n]);
        }
    }
#pragma unroll
    for (int n = 0; n < 8; n++)
        g_h[(base + warp * 8 + n) * C + lane] = acc[n];
}

// ------------------------- CSR gather (no atomics) ---------------------------
__global__ void k_gather(int sel, const float* __restrict__ b) {
    float* __restrict__ agg = (float*)selbuf(sel);
    const float* __restrict__ h = g_h;
    int lane = threadIdx.x & 31;
    int i = blockIdx.x * (blockDim.x >> 5) + (threadIdx.x >> 5);
    if (i >= Nn) return;
    int e  = g_rowptr[i];
    int e1 = g_rowptr[i + 1];
    float acc = h[i * C + lane] * g_dinv[i] + b[lane];
    for (; e + 8 <= e1; e += 8) {
        int2 p0 = g_edge[e + 0];
        int2 p1 = g_edge[e + 1];
        int2 p2 = g_edge[e + 2];
        int2 p3 = g_edge[e + 3];
        int2 p4 = g_edge[e + 4];
        int2 p5 = g_edge[e + 5];
        int2 p6 = g_edge[e + 6];
        int2 p7 = g_edge[e + 7];
        float v0 = h[p0.x * C + lane] * __int_as_float(p0.y);
        float v1 = h[p1.x * C + lane] * __int_as_float(p1.y);
        float v2 = h[p2.x * C + lane] * __int_as_float(p2.y);
        float v3 = h[p3.x * C + lane] * __int_as_float(p3.y);
        float v4 = h[p4.x * C + lane] * __int_as_float(p4.y);
        float v5 = h[p5.x * C + lane] * __int_as_float(p5.y);
        float v6 = h[p6.x * C + lane] * __int_as_float(p6.y);
        float v7 = h[p7.x * C + lane] * __int_as_float(p7.y);
        acc += ((v0 + v1) + (v2 + v3)) + ((v4 + v5) + (v6 + v7));
    }
    for (; e < e1; e++) {
        int2 p = g_edge[e];
        acc += h[p.x * C + lane] * __int_as_float(p.y);
    }
    agg[i * C + lane] = acc;
}

// ------------------------- BN stats: per-block fp32 partials ------------------
__global__ void k_stats(int sel, int n, int pass) {
    const float* __restrict__ a = selbuf(sel);
    int lane = threadIdx.x & 31, warp = threadIdx.x >> 5;
    int nwt = gridDim.x * 8;
    float s = 0.f, q = 0.f;
    for (int i = blockIdx.x * 8 + warp; i < n; i += nwt) {
        float v = a[i * C + lane];
        s += v;
        q += v * v;
    }
    __shared__ float ss[8][32], sq[8][32];
    ss[warp][lane] = s;
    sq[warp][lane] = q;
    __syncthreads();
    if (warp == 0) {
        float S = 0.f, Q = 0.f;
#pragma unroll
        for (int w = 0; w < 8; w++) { S += ss[w][lane]; Q += sq[w][lane]; }
        g_part[pass * (SBLK * 64) + blockIdx.x * 64 + lane]      = S;
        g_part[pass * (SBLK * 64) + blockIdx.x * 64 + 32 + lane] = Q;
    }
}

// finalize: sum partials (fp64 registers only), emit scale/shift per channel
__global__ void k_finalize(int pass, int nb, float n,
                           const float* __restrict__ gamma,
                           const float* __restrict__ beta) {
    int c = threadIdx.x;   // 32 threads
    double S = 0.0, Q = 0.0;
    const float* p = &g_part[pass * (SBLK * 64)];
    for (int b = 0; b < nb; b++) {
        S += (double)p[b * 64 + c];
        Q += (double)p[b * 64 + 32 + c];
    }
    double m   = S / (double)n;
    double var = Q / (double)n - m * m;
    if (var < 0.0) var = 0.0;
    float r  = rsqrtf((float)var + EPSF);
    float sc = r * gamma[c];
    g_bnco[pass * 64 + c]      = sc;
    g_bnco[pass * 64 + 32 + c] = beta[c] - (float)m * sc;
}

// ---------------- fused BN-apply + ReLU + matmul (32->32), register-blocked ---
__global__ void k_mm_small(int selIn, int pass,
                           const float* __restrict__ W) {
    const float* __restrict__ ain = selbuf(selIn);
    __shared__ float Xs[64 * C];
    __shared__ float Ws[C * C];
    __shared__ float bn[64];
    int t = threadIdx.x;
    int base = blockIdx.x * 64;
    if (t < 64) bn[t] = g_bnco[pass * 64 + t];
    {
        const float4* w4 = (const float4*)W;
        float4* Ws4 = (float4*)Ws;
        for (int i = t; i < C * C / 4; i += 256) Ws4[i] = w4[i];
    }
    __syncthreads();
    for (int i = t; i < 64 * C; i += 256) {
        int ch = i & 31;
        float a = ain[base * C + i];
        Xs[i] = fmaxf(a * bn[ch] + bn[32 + ch], 0.f);
    }
    __syncthreads();
    int warp = t >> 5, lane = t & 31;
    float acc[8] = {0.f, 0.f, 0.f, 0.f, 0.f, 0.f, 0.f, 0.f};
    const float* xw = Xs + warp * 8 * C;
#pragma unroll
    for (int k4 = 0; k4 < C / 4; k4++) {
        float w0 = Ws[(k4 * 4 + 0) * C + lane];
        float w1 = Ws[(k4 * 4 + 1) * C + lane];
        float w2 = Ws[(k4 * 4 + 2) * C + lane];
        float w3 = Ws[(k4 * 4 + 3) * C + lane];
#pragma unroll
        for (int n = 0; n < 8; n++) {
            float4 xv = ((const float4*)(xw + n * C))[k4];
            acc[n] = fmaf(xv.x, w0, acc[n]);
            acc[n] = fmaf(xv.y, w1, acc[n]);
            acc[n] = fmaf(xv.z, w2, acc[n]);
            acc[n] = fmaf(xv.w, w3, acc[n]);
        }
    }
#pragma unroll
    for (int n = 0; n < 8; n++)
        g_h[(base + warp * 8 + n) * C + lane] = acc[n];
}

// ------------------------- pooling: sum nodes into graphs --------------------
__global__ void k_pool(const void* __restrict__ batchv) {
    int lane = threadIdx.x & 31;
    int i = blockIdx.x * (blockDim.x >> 5) + (threadIdx.x >> 5);
    if (i >= Nn) return;
    int b;
    if (g_is64) b = (int)((const long long*)batchv)[i];
    else        b = ((const int*)batchv)[i];
    b = min(max(b, 0), Gg - 1);
    atomicAdd(&g_pool[b * C + lane], g_aggA[i * C + lane]);
}

// ------------------------- MLP head -------------------------
__global__ void k_mlp_mm1(const float* __restrict__ M1, const float* __restrict__ mb1) {
    __shared__ float Ws[C * C];
    for (int t = threadIdx.x; t < C * C; t += blockDim.x) Ws[t] = M1[t];
    __syncthreads();
    int warp = threadIdx.x >> 5, lane = threadIdx.x & 31;
    int g = blockIdx.x * 8 + warp;
    if (g >= Gg) return;
    float z = g_pool[g * C + lane];
    float acc = mb1[lane];
#pragma unroll
    for (int k = 0; k < C; k++) {
        float zk = __shfl_sync(0xffffffffu, z, k);
        acc = fmaf(zk, Ws[k * C + lane], acc);
    }
    g_mlpA[g * C + lane] = acc;
}

__global__ void k_mlp_mm2(const float* __restrict__ M2, const float* __restrict__ mb2) {
    __shared__ float Ws[C * C];
    for (int t = threadIdx.x; t < C * C; t += blockDim.x) Ws[t] = M2[t];
    __syncthreads();
    int warp = threadIdx.x >> 5, lane = threadIdx.x & 31;
    int g = blockIdx.x * 8 + warp;
    if (g >= Gg) return;
    float sc = g_bnco[2 * 64 + lane];
    float sh = g_bnco[2 * 64 + 32 + lane];
    float a = g_mlpA[g * C + lane];
    float z = fmaxf(a * sc + sh, 0.f);
    float acc = mb2[lane];
#pragma unroll
    for (int k = 0; k < C; k++) {
        float zk = __shfl_sync(0xffffffffu, z, k);
        acc = fmaf(zk, Ws[k * C + lane], acc);
    }
    g_mlpB[g * C + lane] = acc;
}

__global__ void k_mlp_out(const float* __restrict__ M3, const float* __restrict__ mb3,
                          float* __restrict__ out) {
    int lane = threadIdx.x & 31;
    int g = blockIdx.x * (blockDim.x >> 5) + (threadIdx.x >> 5);
    if (g >= Gg) return;
    float sc = g_bnco[3 * 64 + lane];
    float sh = g_bnco[3 * 64 + 32 + lane];
    float v  = g_mlpB[g * C + lane];
    float z  = fmaxf(v * sc + sh, 0.f);
    float t  = z * M3[lane];
#pragma unroll
    for (int o = 16; o; o >>= 1) t += __shfl_down_sync(0xffffffffu, t, o);
    if (lane == 0) out[g] = t + mb3[0];
}

// ------------------------- launch -------------------------
extern "C" void kernel_launch(void* const* d_in, const int* in_sizes, int n_in,
                              void* d_out, int out_size) {
    (void)in_sizes; (void)n_in; (void)out_size;
    const float* x     = (const float*)d_in[0];
    const void*  ei    = d_in[1];
    const void*  batch = d_in[2];
    const float* W1  = (const float*)d_in[3];
    const float* b1  = (const float*)d_in[4];
    const float* gm1 = (const float*)d_in[5];
    const float* be1 = (const float*)d_in[6];
    const float* W2  = (const float*)d_in[7];
    const float* b2  = (const float*)d_in[8];
    const float* gm2 = (const float*)d_in[9];
    const float* be2 = (const float*)d_in[10];
    const float* W3  = (const float*)d_in[11];
    const float* b3  = (const float*)d_in[12];
    const float* M1  = (const float*)d_in[13];
    const float* mb1 = (const float*)d_in[14];
    const float* mg1 = (const float*)d_in[15];
    const float* mbe1= (const float*)d_in[16];
    const float* M2  = (const float*)d_in[17];
    const float* mb2 = (const float*)d_in[18];
    const float* mg2 = (const float*)d_in[19];
    const float* mbe2= (const float*)d_in[20];
    const float* M3  = (const float*)d_in[21];
    const float* mb3 = (const float*)d_in[22];
    float* out = (float*)d_out;

    const int TB = 256;
    k_init<<<800, TB>>>((const unsigned int*)ei);          // 0
    k_prep_edges<<<(Ee + TB - 1) / TB, TB>>>(ei);          // 1
    k_scan1<<<NSB, SCB>>>();                               // 2
    k_mm1<<<Nn / 64, TB>>>(x, W1);                         // 3 (ncu capture target)
    k_scan2<<<1, 1024>>>();                                // 4
    k_scan3<<<NSB, SCB>>>();                               // 5
    k_sort<<<(Ee + TB - 1) / TB, TB>>>();                  // 6

    // layer 1: conv(x) -> aggA
    k_gather<<<Nn / 8, TB>>>(0, b1);
    k_stats<<<SBLK, TB>>>(0, Nn, 0);
    k_finalize<<<1, 32>>>(0, SBLK, (float)Nn, gm1, be1);

    // layer 2: relu(bn(aggA)) @ W2 -> aggB
    k_mm_small<<<Nn / 64, TB>>>(0, 0, W2);
    k_gather<<<Nn / 8, TB>>>(1, b2);
    k_stats<<<SBLK, TB>>>(1, Nn, 1);
    k_finalize<<<1, 32>>>(1, SBLK, (float)Nn, gm2, be2);

    // layer 3: relu(bn(aggB)) @ W3 -> aggA (no bn after)
    k_mm_small<<<Nn / 64, TB>>>(1, 1, W3);
    k_gather<<<Nn / 8, TB>>>(0, b3);

    // pool + MLP head
    k_pool<<<Nn / 8, TB>>>(batch);
    k_mlp_mm1<<<Gg / 8, TB>>>(M1, mb1);
    k_stats<<<SBLK_G, TB>>>(2, Gg, 2);
    k_finalize<<<1, 32>>>(2, SBLK_G, (float)Gg, mg1, mbe1);
    k_mlp_mm2<<<Gg / 8, TB>>>(M2, mb2);
    k_stats<<<SBLK_G, TB>>>(3, Gg, 3);
    k_finalize<<<1, 32>>>(3, SBLK_G, (float)Gg, mg2, mbe2);
    k_mlp_out<<<Gg / 8, TB>>>(M3, mb3, out);
}

// round 10
// speedup vs baseline: 1.9828x; 1.1501x over previous
#include <cuda_runtime.h>

#define Nn 200000
#define Ee 6400000
#define EPAD (Ee + 4 * Nn)
#define Gg 1024
#define C  32
#define INC 128
#define EPSF 1e-5f
#define SBLK 128          // blocks for node-level BN stats
#define SBLK_G 8          // blocks for graph-level BN stats
#define SCB 256           // nodes per scan block
#define NSB ((Nn + SCB - 1) / SCB)   // 782 scan blocks

// ------------------------- scratch (device globals) -------------------------
__device__ int    g_src[Ee];
__device__ int    g_dst[Ee];
__device__ int    g_edges[EPAD];      // CSR-sorted src per dst, 4-padded (pad = Nn)
__device__ int    g_degi[Nn];
__device__ int    g_rowptr[Nn + 1];   // 4-aligned segment starts
__device__ int    g_cursor[Nn];
__device__ int    g_bsum[NSB];
__device__ int    g_boff[NSB];
__device__ float  g_dis[Nn];
__device__ float  g_h[(Nn + 1) * C];  // h' = h*dis; row Nn stays zero (pad target)
__device__ float  g_aggA[Nn * C];
__device__ float  g_aggB[Nn * C];
__device__ float  g_mlpA[Gg * C];
__device__ float  g_mlpB[Gg * C];
__device__ float  g_pool[Gg * C];
__device__ float  g_part[4 * SBLK * 64];  // per-pass, per-block {sum[32], sumsq[32]}
__device__ float  g_bnco[4 * 64];         // per-pass {scale[32], shift[32]}
__device__ int    g_is64;                 // 1 if index inputs are int64, 0 if int32

__device__ __forceinline__ const float* selbuf(int s) {
    if (s == 0) return g_aggA;
    if (s == 1) return g_aggB;
    if (s == 2) return g_mlpA;
    return g_mlpB;
}

// ------------------------- init: dtype detect + zero + pad prefill -----------
__global__ void k_init(const unsigned int* __restrict__ w) {
    if (blockIdx.x == 0 && threadIdx.x < 32) {
        unsigned int acc = 0;
        for (int i = threadIdx.x; i < 2048; i += 32)
            if (i & 1) acc |= w[i];
#pragma unroll
        for (int o = 16; o; o >>= 1) acc |= __shfl_down_sync(0xffffffffu, acc, o);
        if (threadIdx.x == 0) g_is64 = (acc == 0u) ? 1 : 0;
    }
    int idx = blockIdx.x * blockDim.x + threadIdx.x;
    int stride = gridDim.x * blockDim.x;
    for (int i = idx; i < Nn; i += stride)      g_degi[i] = 0;
    for (int i = idx; i < Gg * C; i += stride)  g_pool[i] = 0.f;
    for (int i = idx; i < EPAD; i += stride)    g_edges[i] = Nn;   // pad -> zero row
    for (int i = idx; i < C; i += stride)       g_h[Nn * C + i] = 0.f;
}

// convert indices -> clamped int32, count in-degree
__global__ void k_prep_edges(const void* __restrict__ eiv) {
    int e = blockIdx.x * blockDim.x + threadIdx.x;
    if (e >= Ee) return;
    int s, d;
    if (g_is64) {
        const long long* ei = (const long long*)eiv;
        s = (int)ei[e];
        d = (int)ei[Ee + e];
    } else {
        const int* ei = (const int*)eiv;
        s = ei[e];
        d = ei[Ee + e];
    }
    s = min(max(s, 0), Nn - 1);
    d = min(max(d, 0), Nn - 1);
    g_src[e] = s;
    g_dst[e] = d;
    atomicAdd(&g_degi[d], 1);
}

// ------------------------- multi-block exclusive scan over PADDED degrees ----
__global__ void k_scan1() {
    __shared__ int sh[SCB / 32];
    int t = threadIdx.x;
    int i = blockIdx.x * SCB + t;
    int v = (i < Nn) ? ((g_degi[i] + 3) & ~3) : 0;
#pragma unroll
    for (int o = 16; o; o >>= 1) v += __shfl_down_sync(0xffffffffu, v, o);
    if ((t & 31) == 0) sh[t >> 5] = v;
    __syncthreads();
    if (t < SCB / 32) {
        int s = sh[t];
#pragma unroll
        for (int o = SCB / 64; o; o >>= 1) s += __shfl_down_sync(0xffffffffu, s, o);
        if (t == 0) g_bsum[blockIdx.x] = s;
    }
}

__global__ void k_scan2() {
    __shared__ int bs[1024];
    int t = threadIdx.x;
    int v = (t < NSB) ? g_bsum[t] : 0;
    bs[t] = v;
    __syncthreads();
    for (int o = 1; o < 1024; o <<= 1) {
        int u = (t >= o) ? bs[t - o] : 0;
        __syncthreads();
        bs[t] += u;
        __syncthreads();
    }
    if (t < NSB) g_boff[t] = bs[t] - v;          // exclusive
    if (t == NSB - 1) g_rowptr[Nn] = bs[t];      // total padded count
}

__global__ void k_scan3() {
    __shared__ int sh[SCB];
    int t = threadIdx.x;
    int i = blockIdx.x * SCB + t;
    int deg = (i < Nn) ? g_degi[i] : 0;
    int pdeg = (deg + 3) & ~3;
    sh[t] = pdeg;
    __syncthreads();
    int incl = pdeg;
    for (int o = 1; o < SCB; o <<= 1) {
        int u = (t >= o) ? sh[t - o] : 0;
        __syncthreads();
        incl += u;
        sh[t] = incl;
        __syncthreads();
    }
    if (i < Nn) {
        int off = g_boff[blockIdx.x] + incl - pdeg;
        g_rowptr[i] = off;
        g_cursor[i] = off;
        g_dis[i] = rsqrtf((float)deg + 1.0f);
    }
}

// ------------------------- counting-sort edges into padded CSR ---------------
__global__ void k_sort() {
    int e = blockIdx.x * blockDim.x + threadIdx.x;
    if (e >= Ee) return;
    int s = g_src[e], d = g_dst[e];
    int pos = atomicAdd(&g_cursor[d], 1);
    g_edges[pos] = s;
}

// ------------------------- layer 1 matmul (128 -> 32), register-blocked ------
// writes h' = (x @ W1) * dis  rowwise   (MUST run after k_scan3!)
__global__ void k_mm1(const float* __restrict__ x,
                      const float* __restrict__ W1) {
    __shared__ float Xs[64 * INC];
    __shared__ float Ws[INC * C];
    int t = threadIdx.x;
    int base = blockIdx.x * 64;
    {
        const float4* x4 = (const float4*)(x + (size_t)base * INC);
        float4* Xs4 = (float4*)Xs;
        for (int i = t; i < 64 * INC / 4; i += 256) Xs4[i] = x4[i];
        const float4* w4 = (const float4*)W1;
        float4* Ws4 = (float4*)Ws;
        for (int i = t; i < INC * C / 4; i += 256) Ws4[i] = w4[i];
    }
    __syncthreads();
    int warp = t >> 5, lane = t & 31;
    float acc[8] = {0.f, 0.f, 0.f, 0.f, 0.f, 0.f, 0.f, 0.f};
    const float* xw = Xs + warp * 8 * INC;
#pragma unroll 4
    for (int k4 = 0; k4 < INC / 4; k4++) {
        float w0 = Ws[(k4 * 4 + 0) * C + lane];
        float w1 = Ws[(k4 * 4 + 1) * C + lane];
        float w2 = Ws[(k4 * 4 + 2) * C + lane];
        float w3 = Ws[(k4 * 4 + 3) * C + lane];
#pragma unroll
        for (int n = 0; n < 8; n++) {
            float4 xv = ((const float4*)(xw + n * INC))[k4];
            acc[n] = fmaf(xv.x, w0, acc[n]);
            acc[n] = fmaf(xv.y, w1, acc[n]);
            acc[n] = fmaf(xv.z, w2, acc[n]);
            acc[n] = fmaf(xv.w, w3, acc[n]);
        }
    }
#pragma unroll
    for (int n = 0; n < 8; n++) {
        int i = base + warp * 8 + n;
        g_h[i * C + lane] = acc[n] * g_dis[i];
    }
}

// ------------------------- CSR gather (int4 edges, dis folded) ---------------
// agg[i] = dis[i]*(sum h'[src] + h'[i]) + b ; pads hit zero row Nn
__global__ void k_gather(int sel, const float* __restrict__ b) {
    float* __restrict__ agg = (float*)selbuf(sel);
    const float* __restrict__ h = g_h;
    int lane = threadIdx.x & 31;
    int i = blockIdx.x * (blockDim.x >> 5) + (threadIdx.x >> 5);
    if (i >= Nn) return;
    const int4* ep = (const int4*)(g_edges + g_rowptr[i]);
    int ng = (g_degi[i] + 3) >> 2;          // int4 groups (pad-covered)
    float acc = h[i * C + lane];            // self term (h')
    int g4 = 0;
    for (; g4 + 4 <= ng; g4 += 4) {
        int4 pa = ep[g4 + 0];
        int4 pb = ep[g4 + 1];
        int4 pc = ep[g4 + 2];
        int4 pd = ep[g4 + 3];
        float v0 = h[pa.x * C + lane], v1 = h[pa.y * C + lane];
        float v2 = h[pa.z * C + lane], v3 = h[pa.w * C + lane];
        float v4 = h[pb.x * C + lane], v5 = h[pb.y * C + lane];
        float v6 = h[pb.z * C + lane], v7 = h[pb.w * C + lane];
        float v8 = h[pc.x * C + lane], v9 = h[pc.y * C + lane];
        float va = h[pc.z * C + lane], vb = h[pc.w * C + lane];
        float vc = h[pd.x * C + lane], vd = h[pd.y * C + lane];
        float ve = h[pd.z * C + lane], vf = h[pd.w * C + lane];
        acc += (((v0 + v1) + (v2 + v3)) + ((v4 + v5) + (v6 + v7)))
             + (((v8 + v9) + (va + vb)) + ((vc + vd) + (ve + vf)));
    }
    for (; g4 < ng; g4++) {
        int4 p = ep[g4];
        float v0 = h[p.x * C + lane], v1 = h[p.y * C + lane];
        float v2 = h[p.z * C + lane], v3 = h[p.w * C + lane];
        acc += (v0 + v1) + (v2 + v3);
    }
    agg[i * C + lane] = fmaf(acc, g_dis[i], b[lane]);
}

// ------------------------- BN stats: per-block fp32 partials ------------------
__global__ void k_stats(int sel, int n, int pass) {
    const float* __restrict__ a = selbuf(sel);
    int lane = threadIdx.x & 31, warp = threadIdx.x >> 5;
    int nwt = gridDim.x * 8;
    float s = 0.f, q = 0.f;
    for (int i = blockIdx.x * 8 + warp; i < n; i += nwt) {
        float v = a[i * C + lane];
        s += v;
        q += v * v;
    }
    __shared__ float ss[8][32], sq[8][32];
    ss[warp][lane] = s;
    sq[warp][lane] = q;
    __syncthreads();
    if (warp == 0) {
        float S = 0.f, Q = 0.f;
#pragma unroll
        for (int w = 0; w < 8; w++) { S += ss[w][lane]; Q += sq[w][lane]; }
        g_part[pass * (SBLK * 64) + blockIdx.x * 64 + lane]      = S;
        g_part[pass * (SBLK * 64) + blockIdx.x * 64 + 32 + lane] = Q;
    }
}

// finalize: sum partials (fp64 registers only), emit scale/shift per channel
__global__ void k_finalize(int pass, int nb, float n,
                           const float* __restrict__ gamma,
                           const float* __restrict__ beta) {
    int c = threadIdx.x;   // 32 threads
    double S = 0.0, Q = 0.0;
    const float* p = &g_part[pass * (SBLK * 64)];
    for (int b = 0; b < nb; b++) {
        S += (double)p[b * 64 + c];
        Q += (double)p[b * 64 + 32 + c];
    }
    double m   = S / (double)n;
    double var = Q / (double)n - m * m;
    if (var < 0.0) var = 0.0;
    float r  = rsqrtf((float)var + EPSF);
    float sc = r * gamma[c];
    g_bnco[pass * 64 + c]      = sc;
    g_bnco[pass * 64 + 32 + c] = beta[c] - (float)m * sc;
}

// -------- fused BN-apply + ReLU + matmul (32->32); writes h' = out*dis -------
__global__ void k_mm_small(int selIn, int pass,
                           const float* __restrict__ W) {
    const float* __restrict__ ain = selbuf(selIn);
    __shared__ float Xs[64 * C];
    __shared__ float Ws[C * C];
    __shared__ float bn[64];
    int t = threadIdx.x;
    int base = blockIdx.x * 64;
    if (t < 64) bn[t] = g_bnco[pass * 64 + t];
    {
        const float4* w4 = (const float4*)W;
        float4* Ws4 = (float4*)Ws;
        for (int i = t; i < C * C / 4; i += 256) Ws4[i] = w4[i];
    }
    __syncthreads();
    for (int i = t; i < 64 * C; i += 256) {
        int ch = i & 31;
        float a = ain[base * C + i];
        Xs[i] = fmaxf(a * bn[ch] + bn[32 + ch], 0.f);
    }
    __syncthreads();
    int warp = t >> 5, lane = t & 31;
    float acc[8] = {0.f, 0.f, 0.f, 0.f, 0.f, 0.f, 0.f, 0.f};
    const float* xw = Xs + warp * 8 * C;
#pragma unroll
    for (int k4 = 0; k4 < C / 4; k4++) {
        float w0 = Ws[(k4 * 4 + 0) * C + lane];
        float w1 = Ws[(k4 * 4 + 1) * C + lane];
        float w2 = Ws[(k4 * 4 + 2) * C + lane];
        float w3 = Ws[(k4 * 4 + 3) * C + lane];
#pragma unroll
        for (int n = 0; n < 8; n++) {
            float4 xv = ((const float4*)(xw + n * C))[k4];
            acc[n] = fmaf(xv.x, w0, acc[n]);
            acc[n] = fmaf(xv.y, w1, acc[n]);
            acc[n] = fmaf(xv.z, w2, acc[n]);
            acc[n] = fmaf(xv.w, w3, acc[n]);
        }
    }
#pragma unroll
    for (int n = 0; n < 8; n++) {
        int i = base + warp * 8 + n;
        g_h[i * C + lane] = acc[n] * g_dis[i];
    }
}

// ------------------------- pooling: sum nodes into graphs --------------------
__global__ void k_pool(const void* __restrict__ batchv) {
    int lane = threadIdx.x & 31;
    int i = blockIdx.x * (blockDim.x >> 5) + (threadIdx.x >> 5);
    if (i >= Nn) return;
    int b;
    if (g_is64) b = (int)((const long long*)batchv)[i];
    else        b = ((const int*)batchv)[i];
    b = min(max(b, 0), Gg - 1);
    atomicAdd(&g_pool[b * C + lane], g_aggA[i * C + lane]);
}

// ------------------------- MLP head -------------------------
__global__ void k_mlp_mm1(const float* __restrict__ M1, const float* __restrict__ mb1) {
    __shared__ float Ws[C * C];
    for (int t = threadIdx.x; t < C * C; t += blockDim.x) Ws[t] = M1[t];
    __syncthreads();
    int warp = threadIdx.x >> 5, lane = threadIdx.x & 31;
    int g = blockIdx.x * 8 + warp;
    if (g >= Gg) return;
    float z = g_pool[g * C + lane];
    float acc = mb1[lane];
#pragma unroll
    for (int k = 0; k < C; k++) {
        float zk = __shfl_sync(0xffffffffu, z, k);
        acc = fmaf(zk, Ws[k * C + lane], acc);
    }
    g_mlpA[g * C + lane] = acc;
}

__global__ void k_mlp_mm2(const float* __restrict__ M2, const float* __restrict__ mb2) {
    __shared__ float Ws[C * C];
    for (int t = threadIdx.x; t < C * C; t += blockDim.x) Ws[t] = M2[t];
    __syncthreads();
    int warp = threadIdx.x >> 5, lane = threadIdx.x & 31;
    int g = blockIdx.x * 8 + warp;
    if (g >= Gg) return;
    float sc = g_bnco[2 * 64 + lane];
    float sh = g_bnco[2 * 64 + 32 + lane];
    float a = g_mlpA[g * C + lane];
    float z = fmaxf(a * sc + sh, 0.f);
    float acc = mb2[lane];
#pragma unroll
    for (int k = 0; k < C; k++) {
        float zk = __shfl_sync(0xffffffffu, z, k);
        acc = fmaf(zk, Ws[k * C + lane], acc);
    }
    g_mlpB[g * C + lane] = acc;
}

__global__ void k_mlp_out(const float* __restrict__ M3, const float* __restrict__ mb3,
                          float* __restrict__ out) {
    int lane = threadIdx.x & 31;
    int g = blockIdx.x * (blockDim.x >> 5) + (threadIdx.x >> 5);
    if (g >= Gg) return;
    float sc = g_bnco[3 * 64 + lane];
    float sh = g_bnco[3 * 64 + 32 + lane];
    float v  = g_mlpB[g * C + lane];
    float z  = fmaxf(v * sc + sh, 0.f);
    float t  = z * M3[lane];
#pragma unroll
    for (int o = 16; o; o >>= 1) t += __shfl_down_sync(0xffffffffu, t, o);
    if (lane == 0) out[g] = t + mb3[0];
}

// ------------------------- launch -------------------------
extern "C" void kernel_launch(void* const* d_in, const int* in_sizes, int n_in,
                              void* d_out, int out_size) {
    (void)in_sizes; (void)n_in; (void)out_size;
    const float* x     = (const float*)d_in[0];
    const void*  ei    = d_in[1];
    const void*  batch = d_in[2];
    const float* W1  = (const float*)d_in[3];
    const float* b1  = (const float*)d_in[4];
    const float* gm1 = (const float*)d_in[5];
    const float* be1 = (const float*)d_in[6];
    const float* W2  = (const float*)d_in[7];
    const float* b2  = (const float*)d_in[8];
    const float* gm2 = (const float*)d_in[9];
    const float* be2 = (const float*)d_in[10];
    const float* W3  = (const float*)d_in[11];
    const float* b3  = (const float*)d_in[12];
    const float* M1  = (const float*)d_in[13];
    const float* mb1 = (const float*)d_in[14];
    const float* mg1 = (const float*)d_in[15];
    const float* mbe1= (const float*)d_in[16];
    const float* M2  = (const float*)d_in[17];
    const float* mb2 = (const float*)d_in[18];
    const float* mg2 = (const float*)d_in[19];
    const float* mbe2= (const float*)d_in[20];
    const float* M3  = (const float*)d_in[21];
    const float* mb3 = (const float*)d_in[22];
    float* out = (float*)d_out;

    const int TB = 256;
    k_init<<<800, TB>>>((const unsigned int*)ei);          // 0
    k_prep_edges<<<(Ee + TB - 1) / TB, TB>>>(ei);          // 1
    k_scan1<<<NSB, SCB>>>();                               // 2
    k_scan2<<<1, 1024>>>();                                // 3
    k_scan3<<<NSB, SCB>>>();                               // 4  (writes g_dis!)
    k_mm1<<<Nn / 64, TB>>>(x, W1);                         // 5  (reads g_dis)
    k_sort<<<(Ee + TB - 1) / TB, TB>>>();                  // 6

    // layer 1: conv(x) -> aggA
    k_gather<<<Nn / 8, TB>>>(0, b1);
    k_stats<<<SBLK, TB>>>(0, Nn, 0);
    k_finalize<<<1, 32>>>(0, SBLK, (float)Nn, gm1, be1);

    // layer 2: relu(bn(aggA)) @ W2 -> aggB
    k_mm_small<<<Nn / 64, TB>>>(0, 0, W2);
    k_gather<<<Nn / 8, TB>>>(1, b2);
    k_stats<<<SBLK, TB>>>(1, Nn, 1);
    k_finalize<<<1, 32>>>(1, SBLK, (float)Nn, gm2, be2);

    // layer 3: relu(bn(aggB)) @ W3 -> aggA (no bn after)
    k_mm_small<<<Nn / 64, TB>>>(1, 1, W3);
    k_gather<<<Nn / 8, TB>>>(0, b3);

    // pool + MLP head
    k_pool<<<Nn / 8, TB>>>(batch);
    k_mlp_mm1<<<Gg / 8, TB>>>(M1, mb1);
    k_stats<<<SBLK_G, TB>>>(2, Gg, 2);
    k_finalize<<<1, 32>>>(2, SBLK_G, (float)Gg, mg1, mbe1);
    k_mlp_mm2<<<Gg / 8, TB>>>(M2, mb2);
    k_stats<<<SBLK_G, TB>>>(3, Gg, 3);
    k_finalize<<<1, 32>>>(3, SBLK_G, (float)Gg, mg2, mbe2);
    k_mlp_out<<<Gg / 8, TB>>>(M3, mb3, out);
}

// round 11
// speedup vs baseline: 2.1925x; 1.1057x over previous
#include <cuda_runtime.h>

#define Nn 200000
#define Ee 6400000
#define EPAD (Ee + 4 * Nn)
#define Gg 1024
#define C  32
#define INC 128
#define EPSF 1e-5f
#define SBLK 128          // partial slots for node-level BN stats
#define SBLK_G 8          // blocks for graph-level BN stats
#define SCB 256           // nodes per scan block
#define NSB ((Nn + SCB - 1) / SCB)   // 782 scan blocks

// ------------------------- scratch (device globals) -------------------------
__device__ int    g_src[Ee];
__device__ int    g_dst[Ee];
__device__ int    g_edges[EPAD];      // CSR-sorted src per dst, 4-padded (pad = Nn)
__device__ int    g_degi[Nn];
__device__ int    g_rowptr[Nn + 1];   // 4-aligned segment starts
__device__ int    g_cursor[Nn];
__device__ int    g_bsum[NSB];
__device__ int    g_boff[NSB];
__device__ float  g_dis[Nn];
__device__ float  g_h[(Nn + 1) * C];  // h' = h*dis; row Nn stays zero (pad target)
__device__ float  g_aggA[Nn * C];
__device__ float  g_aggB[Nn * C];
__device__ float  g_mlpA[Gg * C];
__device__ float  g_mlpB[Gg * C];
__device__ float  g_pool[Gg * C];
__device__ float  g_part[4 * SBLK * 64];  // per-pass {sum[32], sumsq[32]} slots
__device__ float  g_bnco[4 * 64];         // per-pass {scale[32], shift[32]}
__device__ int    g_is64;                 // 1 if index inputs are int64, 0 if int32

__device__ __forceinline__ const float* selbuf(int s) {
    if (s == 0) return g_aggA;
    if (s == 1) return g_aggB;
    if (s == 2) return g_mlpA;
    return g_mlpB;
}

// ------------------------- init: dtype detect + zero + pad prefill -----------
__global__ void k_init(const unsigned int* __restrict__ w) {
    if (blockIdx.x == 0 && threadIdx.x < 32) {
        unsigned int acc = 0;
        for (int i = threadIdx.x; i < 2048; i += 32)
            if (i & 1) acc |= w[i];
#pragma unroll
        for (int o = 16; o; o >>= 1) acc |= __shfl_down_sync(0xffffffffu, acc, o);
        if (threadIdx.x == 0) g_is64 = (acc == 0u) ? 1 : 0;
    }
    int idx = blockIdx.x * blockDim.x + threadIdx.x;
    int stride = gridDim.x * blockDim.x;
    for (int i = idx; i < Nn; i += stride)            g_degi[i] = 0;
    for (int i = idx; i < Gg * C; i += stride)        g_pool[i] = 0.f;
    for (int i = idx; i < 2 * SBLK * 64; i += stride) g_part[i] = 0.f;  // fused-stats slots
    for (int i = idx; i < EPAD; i += stride)          g_edges[i] = Nn;  // pad -> zero row
    for (int i = idx; i < C; i += stride)             g_h[Nn * C + i] = 0.f;
}

// convert indices -> clamped int32, count in-degree
__global__ void k_prep_edges(const void* __restrict__ eiv) {
    int e = blockIdx.x * blockDim.x + threadIdx.x;
    if (e >= Ee) return;
    int s, d;
    if (g_is64) {
        const long long* ei = (const long long*)eiv;
        s = (int)ei[e];
        d = (int)ei[Ee + e];
    } else {
        const int* ei = (const int*)eiv;
        s = ei[e];
        d = ei[Ee + e];
    }
    s = min(max(s, 0), Nn - 1);
    d = min(max(d, 0), Nn - 1);
    g_src[e] = s;
    g_dst[e] = d;
    atomicAdd(&g_degi[d], 1);
}

// ------------------------- multi-block exclusive scan over PADDED degrees ----
__global__ void k_scan1() {
    __shared__ int sh[SCB / 32];
    int t = threadIdx.x;
    int i = blockIdx.x * SCB + t;
    int v = (i < Nn) ? ((g_degi[i] + 3) & ~3) : 0;
#pragma unroll
    for (int o = 16; o; o >>= 1) v += __shfl_down_sync(0xffffffffu, v, o);
    if ((t & 31) == 0) sh[t >> 5] = v;
    __syncthreads();
    if (t < SCB / 32) {
        int s = sh[t];
#pragma unroll
        for (int o = SCB / 64; o; o >>= 1) s += __shfl_down_sync(0xffffffffu, s, o);
        if (t == 0) g_bsum[blockIdx.x] = s;
    }
}

__global__ void k_scan2() {
    __shared__ int bs[1024];
    int t = threadIdx.x;
    int v = (t < NSB) ? g_bsum[t] : 0;
    bs[t] = v;
    __syncthreads();
    for (int o = 1; o < 1024; o <<= 1) {
        int u = (t >= o) ? bs[t - o] : 0;
        __syncthreads();
        bs[t] += u;
        __syncthreads();
    }
    if (t < NSB) g_boff[t] = bs[t] - v;          // exclusive
    if (t == NSB - 1) g_rowptr[Nn] = bs[t];      // total padded count
}

__global__ void k_scan3() {
    __shared__ int sh[SCB];
    int t = threadIdx.x;
    int i = blockIdx.x * SCB + t;
    int deg = (i < Nn) ? g_degi[i] : 0;
    int pdeg = (deg + 3) & ~3;
    sh[t] = pdeg;
    __syncthreads();
    int incl = pdeg;
    for (int o = 1; o < SCB; o <<= 1) {
        int u = (t >= o) ? sh[t - o] : 0;
        __syncthreads();
        incl += u;
        sh[t] = incl;
        __syncthreads();
    }
    if (i < Nn) {
        int off = g_boff[blockIdx.x] + incl - pdeg;
        g_rowptr[i] = off;
        g_cursor[i] = off;
        g_dis[i] = rsqrtf((float)deg + 1.0f);
    }
}

// ------------------------- counting-sort edges into padded CSR ---------------
__global__ void k_sort() {
    int e = blockIdx.x * blockDim.x + threadIdx.x;
    if (e >= Ee) return;
    int s = g_src[e], d = g_dst[e];
    int pos = atomicAdd(&g_cursor[d], 1);
    g_edges[pos] = s;
}

// ---------------- layer 1 matmul (128->32), K-tiled for occupancy ------------
// writes h' = (x @ W1) * dis  rowwise   (runs after k_scan3)
__global__ void k_mm1(const float* __restrict__ x,
                      const float* __restrict__ W1) {
    __shared__ float Xs[64 * 32];     // one 64x32 K-tile
    __shared__ float Ws[INC * C];
    int t = threadIdx.x;
    int base = blockIdx.x * 64;
    {
        const float4* w4 = (const float4*)W1;
        float4* Ws4 = (float4*)Ws;
        for (int i = t; i < INC * C / 4; i += 256) Ws4[i] = w4[i];
    }
    int warp = t >> 5, lane = t & 31;
    float acc[8] = {0.f, 0.f, 0.f, 0.f, 0.f, 0.f, 0.f, 0.f};
    const float4* x4 = (const float4*)x;
    float4* Xs4 = (float4*)Xs;
#pragma unroll
    for (int kt = 0; kt < 4; kt++) {
        __syncthreads();              // protect Xs overwrite (and Ws on kt=0)
        for (int i = t; i < 64 * 8; i += 256) {
            int row = i >> 3, c4 = i & 7;
            Xs4[i] = x4[(size_t)(base + row) * 32 + kt * 8 + c4];
        }
        __syncthreads();
        const float* xw = Xs + warp * 8 * 32;
#pragma unroll
        for (int k4 = 0; k4 < 8; k4++) {
            int k = kt * 32 + k4 * 4;
            float w0 = Ws[(k + 0) * C + lane];
            float w1 = Ws[(k + 1) * C + lane];
            float w2 = Ws[(k + 2) * C + lane];
            float w3 = Ws[(k + 3) * C + lane];
#pragma unroll
            for (int n = 0; n < 8; n++) {
                float4 xv = ((const float4*)(xw + n * 32))[k4];
                acc[n] = fmaf(xv.x, w0, acc[n]);
                acc[n] = fmaf(xv.y, w1, acc[n]);
                acc[n] = fmaf(xv.z, w2, acc[n]);
                acc[n] = fmaf(xv.w, w3, acc[n]);
            }
        }
    }
#pragma unroll
    for (int n = 0; n < 8; n++) {
        int i = base + warp * 8 + n;
        g_h[i * C + lane] = acc[n] * g_dis[i];
    }
}

// ------------- CSR gather core: acc = h'[self] + sum h'[src] -----------------
__device__ __forceinline__ float gather_acc(int i, int lane) {
    const float* __restrict__ h = g_h;
    const int4* ep = (const int4*)(g_edges + g_rowptr[i]);
    int ng = (g_degi[i] + 3) >> 2;
    float acc = h[i * C + lane];
    int g4 = 0;
    for (; g4 + 4 <= ng; g4 += 4) {
        int4 pa = ep[g4 + 0];
        int4 pb = ep[g4 + 1];
        int4 pc = ep[g4 + 2];
        int4 pd = ep[g4 + 3];
        float v0 = h[pa.x * C + lane], v1 = h[pa.y * C + lane];
        float v2 = h[pa.z * C + lane], v3 = h[pa.w * C + lane];
        float v4 = h[pb.x * C + lane], v5 = h[pb.y * C + lane];
        float v6 = h[pb.z * C + lane], v7 = h[pb.w * C + lane];
        float v8 = h[pc.x * C + lane], v9 = h[pc.y * C + lane];
        float va = h[pc.z * C + lane], vb = h[pc.w * C + lane];
        float vc = h[pd.x * C + lane], vd = h[pd.y * C + lane];
        float ve = h[pd.z * C + lane], vf = h[pd.w * C + lane];
        acc += (((v0 + v1) + (v2 + v3)) + ((v4 + v5) + (v6 + v7)))
             + (((v8 + v9) + (va + vb)) + ((vc + vd) + (ve + vf)));
    }
    for (; g4 < ng; g4++) {
        int4 p = ep[g4];
        float v0 = h[p.x * C + lane], v1 = h[p.y * C + lane];
        float v2 = h[p.z * C + lane], v3 = h[p.w * C + lane];
        acc += (v0 + v1) + (v2 + v3);
    }
    return acc;
}

// ----- gather + write agg + fused BN partial stats (layers 1, 2) -------------
// grid must divide Nn exactly (Nn/8 blocks of 8 warps)
__global__ void k_gather_stats(int sel, const float* __restrict__ b, int pass) {
    float* __restrict__ agg = (float*)selbuf(sel);
    __shared__ float shS[32], shQ[32];
    int t = threadIdx.x;
    int lane = t & 31;
    if (t < 32) { shS[t] = 0.f; shQ[t] = 0.f; }
    __syncthreads();
    int i = blockIdx.x * 8 + (t >> 5);
    float out = fmaf(gather_acc(i, lane), g_dis[i], b[lane]);
    agg[i * C + lane] = out;
    atomicAdd(&shS[lane], out);
    atomicAdd(&shQ[lane], out * out);
    __syncthreads();
    if (t < 32) {
        int off = pass * (SBLK * 64) + (blockIdx.x & (SBLK - 1)) * 64;
        atomicAdd(&g_part[off + t],      shS[t]);
        atomicAdd(&g_part[off + 32 + t], shQ[t]);
    }
}

// ----- gather + fused pooling (layer 3): no agg write --------------------------
__global__ void k_gather_pool(const float* __restrict__ b,
                              const void* __restrict__ batchv) {
    int t = threadIdx.x;
    int lane = t & 31;
    int i = blockIdx.x * 8 + (t >> 5);
    float out = fmaf(gather_acc(i, lane), g_dis[i], b[lane]);
    int bi;
    if (g_is64) bi = (int)((const long long*)batchv)[i];
    else        bi = ((const int*)batchv)[i];
    bi = min(max(bi, 0), Gg - 1);
    atomicAdd(&g_pool[bi * C + lane], out);
}

// ------------------------- BN stats (MLP passes only) ------------------------
__global__ void k_stats(int sel, int n, int pass) {
    const float* __restrict__ a = selbuf(sel);
    int lane = threadIdx.x & 31, warp = threadIdx.x >> 5;
    int nwt = gridDim.x * 8;
    float s = 0.f, q = 0.f;
    for (int i = blockIdx.x * 8 + warp; i < n; i += nwt) {
        float v = a[i * C + lane];
        s += v;
        q += v * v;
    }
    __shared__ float ss[8][32], sq[8][32];
    ss[warp][lane] = s;
    sq[warp][lane] = q;
    __syncthreads();
    if (warp == 0) {
        float S = 0.f, Q = 0.f;
#pragma unroll
        for (int w = 0; w < 8; w++) { S += ss[w][lane]; Q += sq[w][lane]; }
        g_part[pass * (SBLK * 64) + blockIdx.x * 64 + lane]      = S;
        g_part[pass * (SBLK * 64) + blockIdx.x * 64 + 32 + lane] = Q;
    }
}

// finalize: sum partials (fp64 registers only), emit scale/shift per channel
__global__ void k_finalize(int pass, int nb, float n,
                           const float* __restrict__ gamma,
                           const float* __restrict__ beta) {
    int c = threadIdx.x;   // 32 threads
    double S = 0.0, Q = 0.0;
    const float* p = &g_part[pass * (SBLK * 64)];
    for (int b = 0; b < nb; b++) {
        S += (double)p[b * 64 + c];
        Q += (double)p[b * 64 + 32 + c];
    }
    double m   = S / (double)n;
    double var = Q / (double)n - m * m;
    if (var < 0.0) var = 0.0;
    float r  = rsqrtf((float)var + EPSF);
    float sc = r * gamma[c];
    g_bnco[pass * 64 + c]      = sc;
    g_bnco[pass * 64 + 32 + c] = beta[c] - (float)m * sc;
}

// -------- fused BN-apply + ReLU + matmul (32->32); writes h' = out*dis -------
__global__ void k_mm_small(int selIn, int pass,
                           const float* __restrict__ W) {
    const float* __restrict__ ain = selbuf(selIn);
    __shared__ float Xs[64 * C];
    __shared__ float Ws[C * C];
    __shared__ float bn[64];
    int t = threadIdx.x;
    int base = blockIdx.x * 64;
    if (t < 64) bn[t] = g_bnco[pass * 64 + t];
    {
        const float4* w4 = (const float4*)W;
        float4* Ws4 = (float4*)Ws;
        for (int i = t; i < C * C / 4; i += 256) Ws4[i] = w4[i];
    }
    __syncthreads();
    for (int i = t; i < 64 * C; i += 256) {
        int ch = i & 31;
        float a = ain[base * C + i];
        Xs[i] = fmaxf(a * bn[ch] + bn[32 + ch], 0.f);
    }
    __syncthreads();
    int warp = t >> 5, lane = t & 31;
    float acc[8] = {0.f, 0.f, 0.f, 0.f, 0.f, 0.f, 0.f, 0.f};
    const float* xw = Xs + warp * 8 * C;
#pragma unroll
    for (int k4 = 0; k4 < C / 4; k4++) {
        float w0 = Ws[(k4 * 4 + 0) * C + lane];
        float w1 = Ws[(k4 * 4 + 1) * C + lane];
        float w2 = Ws[(k4 * 4 + 2) * C + lane];
        float w3 = Ws[(k4 * 4 + 3) * C + lane];
#pragma unroll
        for (int n = 0; n < 8; n++) {
            float4 xv = ((const float4*)(xw + n * C))[k4];
            acc[n] = fmaf(xv.x, w0, acc[n]);
            acc[n] = fmaf(xv.y, w1, acc[n]);
            acc[n] = fmaf(xv.z, w2, acc[n]);
            acc[n] = fmaf(xv.w, w3, acc[n]);
        }
    }
#pragma unroll
    for (int n = 0; n < 8; n++) {
        int i = base + warp * 8 + n;
        g_h[i * C + lane] = acc[n] * g_dis[i];
    }
}

// ------------------------- MLP head -------------------------
__global__ void k_mlp_mm1(const float* __restrict__ M1, const float* __restrict__ mb1) {
    __shared__ float Ws[C * C];
    for (int t = threadIdx.x; t < C * C; t += blockDim.x) Ws[t] = M1[t];
    __syncthreads();
    int warp = threadIdx.x >> 5, lane = threadIdx.x & 31;
    int g = blockIdx.x * 8 + warp;
    if (g >= Gg) return;
    float z = g_pool[g * C + lane];
    float acc = mb1[lane];
#pragma unroll
    for (int k = 0; k < C; k++) {
        float zk = __shfl_sync(0xffffffffu, z, k);
        acc = fmaf(zk, Ws[k * C + lane], acc);
    }
    g_mlpA[g * C + lane] = acc;
}

__global__ void k_mlp_mm2(const float* __restrict__ M2, const float* __restrict__ mb2) {
    __shared__ float Ws[C * C];
    for (int t = threadIdx.x; t < C * C; t += blockDim.x) Ws[t] = M2[t];
    __syncthreads();
    int warp = threadIdx.x >> 5, lane = threadIdx.x & 31;
    int g = blockIdx.x * 8 + warp;
    if (g >= Gg) return;
    float sc = g_bnco[2 * 64 + lane];
    float sh = g_bnco[2 * 64 + 32 + lane];
    float a = g_mlpA[g * C + lane];
    float z = fmaxf(a * sc + sh, 0.f);
    float acc = mb2[lane];
#pragma unroll
    for (int k = 0; k < C; k++) {
        float zk = __shfl_sync(0xffffffffu, z, k);
        acc = fmaf(zk, Ws[k * C + lane], acc);
    }
    g_mlpB[g * C + lane] = acc;
}

__global__ void k_mlp_out(const float* __restrict__ M3, const float* __restrict__ mb3,
                          float* __restrict__ out) {
    int lane = threadIdx.x & 31;
    int g = blockIdx.x * (blockDim.x >> 5) + (threadIdx.x >> 5);
    if (g >= Gg) return;
    float sc = g_bnco[3 * 64 + lane];
    float sh = g_bnco[3 * 64 + 32 + lane];
    float v  = g_mlpB[g * C + lane];
    float z  = fmaxf(v * sc + sh, 0.f);
    float t  = z * M3[lane];
#pragma unroll
    for (int o = 16; o; o >>= 1) t += __shfl_down_sync(0xffffffffu, t, o);
    if (lane == 0) out[g] = t + mb3[0];
}

// ------------------------- launch -------------------------
extern "C" void kernel_launch(void* const* d_in, const int* in_sizes, int n_in,
                              void* d_out, int out_size) {
    (void)in_sizes; (void)n_in; (void)out_size;
    const float* x     = (const float*)d_in[0];
    const void*  ei    = d_in[1];
    const void*  batch = d_in[2];
    const float* W1  = (const float*)d_in[3];
    const float* b1  = (const float*)d_in[4];
    const float* gm1 = (const float*)d_in[5];
    const float* be1 = (const float*)d_in[6];
    const float* W2  = (const float*)d_in[7];
    const float* b2  = (const float*)d_in[8];
    const float* gm2 = (const float*)d_in[9];
    const float* be2 = (const float*)d_in[10];
    const float* W3  = (const float*)d_in[11];
    const float* b3  = (const float*)d_in[12];
    const float* M1  = (const float*)d_in[13];
    const float* mb1 = (const float*)d_in[14];
    const float* mg1 = (const float*)d_in[15];
    const float* mbe1= (const float*)d_in[16];
    const float* M2  = (const float*)d_in[17];
    const float* mb2 = (const float*)d_in[18];
    const float* mg2 = (const float*)d_in[19];
    const float* mbe2= (const float*)d_in[20];
    const float* M3  = (const float*)d_in[21];
    const float* mb3 = (const float*)d_in[22];
    float* out = (float*)d_out;

    const int TB = 256;
    k_init<<<800, TB>>>((const unsigned int*)ei);
    k_prep_edges<<<(Ee + TB - 1) / TB, TB>>>(ei);
    k_scan1<<<NSB, SCB>>>();
    k_scan2<<<1, 1024>>>();
    k_scan3<<<NSB, SCB>>>();                               // writes g_dis
    k_mm1<<<Nn / 64, TB>>>(x, W1);                         // reads g_dis
    k_sort<<<(Ee + TB - 1) / TB, TB>>>();

    // layer 1: conv(x) -> aggA (+fused stats pass 0)
    k_gather_stats<<<Nn / 8, TB>>>(0, b1, 0);
    k_finalize<<<1, 32>>>(0, SBLK, (float)Nn, gm1, be1);

    // layer 2: relu(bn(aggA)) @ W2 -> aggB (+fused stats pass 1)
    k_mm_small<<<Nn / 64, TB>>>(0, 0, W2);
    k_gather_stats<<<Nn / 8, TB>>>(1, b2, 1);
    k_finalize<<<1, 32>>>(1, SBLK, (float)Nn, gm2, be2);

    // layer 3: relu(bn(aggB)) @ W3 -> pooled directly
    k_mm_small<<<Nn / 64, TB>>>(1, 1, W3);
    k_gather_pool<<<Nn / 8, TB>>>(b3, batch);

    // MLP head
    k_mlp_mm1<<<Gg / 8, TB>>>(M1, mb1);
    k_stats<<<SBLK_G, TB>>>(2, Gg, 2);
    k_finalize<<<1, 32>>>(2, SBLK_G, (float)Gg, mg1, mbe1);
    k_mlp_mm2<<<Gg / 8, TB>>>(M2, mb2);
    k_stats<<<SBLK_G, TB>>>(3, Gg, 3);
    k_finalize<<<1, 32>>>(3, SBLK_G, (float)Gg, mg2, mbe2);
    k_mlp_out<<<Gg / 8, TB>>>(M3, mb3, out);
}